// round 5
// baseline (speedup 1.0000x reference)
#include <cuda_runtime.h>
#include <cuda_bf16.h>
#include <cstdint>

// ===========================================================================
// GCN 3-layer encoder.
//  - GEMMs: mma.sync m16n8k16 bf16, bf16-split (Ah@Bh + Ah@Bl + Al@Bh), fp32 acc.
//  - CSR-pull aggregation (no atomics in hot path), bias+self-loop+ReLU fused.
//  - Fork/join dual-stream graph: CSR build overlaps W-prep + GEMM1.
// ===========================================================================

#define MAX_NODES 100000
#define MAX_EDGES 1000000

__device__ float              g_H     [(size_t)MAX_NODES * 128];
__device__ float              g_A     [(size_t)MAX_NODES * 128];
__device__ int                g_cnt   [MAX_NODES];
__device__ int                g_rowptr[MAX_NODES + 1];
__device__ int                g_cursor[MAX_NODES];
__device__ float              g_dinv  [MAX_NODES];
__device__ unsigned long long g_esw   [MAX_EDGES];   // {w:f32 hi, src:i32 lo}
__device__ int                g_bsum  [1024];
__device__ int                g_boff  [1024];
__device__ unsigned short     g_B1h[128 * 128], g_B1l[128 * 128];
__device__ unsigned short     g_B2h[128 * 64],  g_B2l[128 * 64];
__device__ unsigned short     g_B3h[64 * 64],   g_B3l[64 * 64];

// ---------------------------------------------------------------------------
// helpers
// ---------------------------------------------------------------------------
__device__ __forceinline__ uint32_t smem_u32(const void* p) {
    uint32_t a;
    asm("{ .reg .u64 t; cvta.to.shared.u64 t, %1; cvt.u32.u64 %0, t; }"
        : "=r"(a) : "l"(p));
    return a;
}

__device__ __forceinline__ void ldsm_x4(uint32_t& r0, uint32_t& r1,
                                        uint32_t& r2, uint32_t& r3, uint32_t addr) {
    asm volatile("ldmatrix.sync.aligned.m8n8.x4.shared.b16 {%0,%1,%2,%3}, [%4];"
                 : "=r"(r0), "=r"(r1), "=r"(r2), "=r"(r3) : "r"(addr));
}

__device__ __forceinline__ void ldsm_x2(uint32_t& r0, uint32_t& r1, uint32_t addr) {
    asm volatile("ldmatrix.sync.aligned.m8n8.x2.shared.b16 {%0,%1}, [%2];"
                 : "=r"(r0), "=r"(r1) : "r"(addr));
}

__device__ __forceinline__ void mma_bf16(float* c, uint32_t a0, uint32_t a1,
                                         uint32_t a2, uint32_t a3,
                                         uint32_t b0, uint32_t b1) {
    asm volatile(
        "mma.sync.aligned.m16n8k16.row.col.f32.bf16.bf16.f32 "
        "{%0,%1,%2,%3}, {%4,%5,%6,%7}, {%8,%9}, {%0,%1,%2,%3};"
        : "+f"(c[0]), "+f"(c[1]), "+f"(c[2]), "+f"(c[3])
        : "r"(a0), "r"(a1), "r"(a2), "r"(a3), "r"(b0), "r"(b1));
}

// ---------------------------------------------------------------------------
// CSR build
// ---------------------------------------------------------------------------
__global__ void hist_kernel(const int* __restrict__ dst, int* __restrict__ cnt, int m) {
    int e = blockIdx.x * blockDim.x + threadIdx.x;
    if (e < m) atomicAdd(&cnt[dst[e]], 1);
}

__global__ void dinv_kernel(const int* __restrict__ cnt, float* __restrict__ dinv, int n) {
    int i = blockIdx.x * blockDim.x + threadIdx.x;
    if (i < n) dinv[i] = rsqrtf((float)(cnt[i] + 1));
}

__global__ __launch_bounds__(256)
void scan_p1_kernel(const int* __restrict__ cnt, int* __restrict__ bsum, int n) {
    __shared__ int red[256];
    int base = blockIdx.x * 1024;
    int t = threadIdx.x;
    int s = 0;
#pragma unroll
    for (int j = 0; j < 4; j++) {
        int i = base + t * 4 + j;
        if (i < n) s += cnt[i];
    }
    red[t] = s;
    __syncthreads();
    for (int d = 128; d > 0; d >>= 1) {
        if (t < d) red[t] += red[t + d];
        __syncthreads();
    }
    if (t == 0) bsum[blockIdx.x] = red[0];
}

__global__ __launch_bounds__(256)
void scan_p2_kernel(const int* __restrict__ bsum, int* __restrict__ boff,
                    int* __restrict__ rowptr, int n, int nb) {
    __shared__ int sm[256];
    int t = threadIdx.x;
    int v = (t < nb) ? bsum[t] : 0;
    sm[t] = v;
    __syncthreads();
    for (int d = 1; d < 256; d <<= 1) {
        int u = (t >= d) ? sm[t - d] : 0;
        __syncthreads();
        sm[t] += u;
        __syncthreads();
    }
    if (t < nb) boff[t] = sm[t] - v;
    if (t == 255) rowptr[n] = sm[255];
}

__global__ __launch_bounds__(256)
void scan_p3_kernel(const int* __restrict__ cnt, const int* __restrict__ boff,
                    int* __restrict__ rowptr, int* __restrict__ cursor, int n) {
    __shared__ int sm[256];
    int base = blockIdx.x * 1024;
    int t = threadIdx.x;
    int c[4];
    int s = 0;
#pragma unroll
    for (int j = 0; j < 4; j++) {
        int i = base + t * 4 + j;
        c[j] = (i < n) ? cnt[i] : 0;
        s += c[j];
    }
    sm[t] = s;
    __syncthreads();
    for (int d = 1; d < 256; d <<= 1) {
        int u = (t >= d) ? sm[t - d] : 0;
        __syncthreads();
        sm[t] += u;
        __syncthreads();
    }
    int run = boff[blockIdx.x] + sm[t] - s;
#pragma unroll
    for (int j = 0; j < 4; j++) {
        int i = base + t * 4 + j;
        if (i < n) { rowptr[i] = run; cursor[i] = run; }
        run += c[j];
    }
}

__global__ void fill_kernel(const int* __restrict__ src, const int* __restrict__ dst,
                            const float* __restrict__ dinv, int* __restrict__ cursor,
                            unsigned long long* __restrict__ esw, int m) {
    int e = blockIdx.x * blockDim.x + threadIdx.x;
    if (e >= m) return;
    int s = src[e];
    int d = dst[e];
    float w = dinv[s] * dinv[d];
    int pos = atomicAdd(&cursor[d], 1);
    esw[pos] = ((unsigned long long)__float_as_uint(w) << 32) | (unsigned)s;
}

// ---------------------------------------------------------------------------
// W prep: split fp32 W[K,N] into bf16 hi/lo stored transposed [n][k].
// ---------------------------------------------------------------------------
template <int K, int N>
__global__ void bprep_kernel(const float* __restrict__ W,
                             unsigned short* __restrict__ hi,
                             unsigned short* __restrict__ lo) {
    int idx = blockIdx.x * 256 + threadIdx.x;   // idx = k*N + n
    if (idx >= K * N) return;
    int n = idx % N;
    int k = idx / N;
    float w = W[idx];
    __nv_bfloat16 h = __float2bfloat16(w);
    __nv_bfloat16 l = __float2bfloat16(w - __bfloat162float(h));
    hi[n * K + k] = __bfloat16_as_ushort(h);
    lo[n * K + k] = __bfloat16_as_ushort(l);
}

// ---------------------------------------------------------------------------
// Tensor-core GEMM: C[M,N] = A[M,K] @ W[K,N], 3x bf16 mma.sync passes.
// CTA: 256 threads (8 warps), BM=128, full K in smem.
// ---------------------------------------------------------------------------
template <int K, int N>
__global__ __launch_bounds__(256)
void gemm_mma_kernel(const float* __restrict__ A,
                     const unsigned short* __restrict__ Bhi,
                     const unsigned short* __restrict__ Blo,
                     float* __restrict__ C, int M) {
    constexpr int SA = (K + 8) * 2;
    constexpr int ABYTES = 128 * SA;
    constexpr int BBYTES = N * SA;
    extern __shared__ char smem[];
    char* sAh = smem;
    char* sAl = smem + ABYTES;
    char* sBh = smem + 2 * ABYTES;
    char* sBl = smem + 2 * ABYTES + BBYTES;

    const int tid = threadIdx.x;
    const int wid = tid >> 5;
    const int lane = tid & 31;
    const int rowBase = blockIdx.x * 128;

    {
        constexpr int CH = N * (K / 8);
        const uint4* bh = (const uint4*)Bhi;
        const uint4* bl = (const uint4*)Blo;
        for (int i = tid; i < CH; i += 256) {
            int r = i / (K / 8), c = i % (K / 8);
            *(uint4*)(sBh + r * SA + c * 16) = bh[i];
            *(uint4*)(sBl + r * SA + c * 16) = bl[i];
        }
    }
    {
        constexpr int F4R = K / 4;
        constexpr int RP = 256 / F4R;
        int r0 = tid / F4R;
        int c4 = tid % F4R;
        for (int r = r0; r < 128; r += RP) {
            int row = rowBase + r;
            float4 v = make_float4(0.f, 0.f, 0.f, 0.f);
            if (row < M) v = *(const float4*)&A[(size_t)row * K + c4 * 4];
            __nv_bfloat16 h0 = __float2bfloat16(v.x);
            __nv_bfloat16 h1 = __float2bfloat16(v.y);
            __nv_bfloat16 h2 = __float2bfloat16(v.z);
            __nv_bfloat16 h3 = __float2bfloat16(v.w);
            __nv_bfloat16 l0 = __float2bfloat16(v.x - __bfloat162float(h0));
            __nv_bfloat16 l1 = __float2bfloat16(v.y - __bfloat162float(h1));
            __nv_bfloat16 l2 = __float2bfloat16(v.z - __bfloat162float(h2));
            __nv_bfloat16 l3 = __float2bfloat16(v.w - __bfloat162float(h3));
            uint2 hp, lp;
            hp.x = (uint32_t)__bfloat16_as_ushort(h0) | ((uint32_t)__bfloat16_as_ushort(h1) << 16);
            hp.y = (uint32_t)__bfloat16_as_ushort(h2) | ((uint32_t)__bfloat16_as_ushort(h3) << 16);
            lp.x = (uint32_t)__bfloat16_as_ushort(l0) | ((uint32_t)__bfloat16_as_ushort(l1) << 16);
            lp.y = (uint32_t)__bfloat16_as_ushort(l2) | ((uint32_t)__bfloat16_as_ushort(l3) << 16);
            *(uint2*)(sAh + r * SA + c4 * 8) = hp;
            *(uint2*)(sAl + r * SA + c4 * 8) = lp;
        }
    }
    __syncthreads();

    constexpr int NCH = N / 8;
    float acc[NCH][4];
#pragma unroll
    for (int i = 0; i < NCH; i++) {
        acc[i][0] = 0.f; acc[i][1] = 0.f; acc[i][2] = 0.f; acc[i][3] = 0.f;
    }

    const uint32_t aH = smem_u32(sAh);
    const uint32_t aL = smem_u32(sAl);
    const uint32_t bH = smem_u32(sBh);
    const uint32_t bL = smem_u32(sBl);
    const uint32_t aoff = (uint32_t)(wid * 16 + (lane & 15)) * SA + (uint32_t)(lane >> 4) * 16;
    const uint32_t boff = (uint32_t)(lane & 7) * SA + (uint32_t)((lane >> 3) & 1) * 16;

#pragma unroll
    for (int kc = 0; kc < K / 16; kc++) {
        uint32_t ah0, ah1, ah2, ah3, al0, al1, al2, al3;
        ldsm_x4(ah0, ah1, ah2, ah3, aH + aoff + kc * 32);
        ldsm_x4(al0, al1, al2, al3, aL + aoff + kc * 32);
#pragma unroll
        for (int nc = 0; nc < NCH; nc++) {
            uint32_t bo = (uint32_t)(nc * 8) * SA + boff + kc * 32;
            uint32_t bh0, bh1, bl0, bl1;
            ldsm_x2(bh0, bh1, bH + bo);
            ldsm_x2(bl0, bl1, bL + bo);
            mma_bf16(acc[nc], ah0, ah1, ah2, ah3, bh0, bh1);
            mma_bf16(acc[nc], ah0, ah1, ah2, ah3, bl0, bl1);
            mma_bf16(acc[nc], al0, al1, al2, al3, bh0, bh1);
        }
    }

    int r0 = rowBase + wid * 16 + (lane >> 2);
    int c0 = (lane & 3) * 2;
#pragma unroll
    for (int nc = 0; nc < NCH; nc++) {
        if (r0 < M)
            *(float2*)&C[(size_t)r0 * N + nc * 8 + c0] = make_float2(acc[nc][0], acc[nc][1]);
        if (r0 + 8 < M)
            *(float2*)&C[(size_t)(r0 + 8) * N + nc * 8 + c0] = make_float2(acc[nc][2], acc[nc][3]);
    }
}

// ---------------------------------------------------------------------------
// CSR pull aggregation, unroll-4 (bias + self-loop + ReLU fused).
// ---------------------------------------------------------------------------
template <int F4, int RELU>
__global__ __launch_bounds__(256)
void aggregate_kernel(const float* __restrict__ H,
                      const int* __restrict__ rowptr,
                      const unsigned long long* __restrict__ esw,
                      const float* __restrict__ dinv,
                      const float* __restrict__ bias,
                      float* __restrict__ Out, int n) {
    constexpr int G = 256 / F4;
    int i = blockIdx.x * G + (threadIdx.x / F4);
    int c = threadIdx.x % F4;
    if (i >= n) return;

    const float4* Hc = (const float4*)H + c;

    float di = dinv[i];
    float wl = di * di;
    float4 h = Hc[(size_t)i * F4];
    float4 b = ((const float4*)bias)[c];
    float4 acc;
    acc.x = fmaf(h.x, wl, b.x);
    acc.y = fmaf(h.y, wl, b.y);
    acc.z = fmaf(h.z, wl, b.z);
    acc.w = fmaf(h.w, wl, b.w);

    int k   = rowptr[i];
    int end = rowptr[i + 1];

    for (; k + 3 < end; k += 4) {
        unsigned long long p0 = __ldg(&esw[k]);
        unsigned long long p1 = __ldg(&esw[k + 1]);
        unsigned long long p2 = __ldg(&esw[k + 2]);
        unsigned long long p3 = __ldg(&esw[k + 3]);
        float4 h0 = Hc[(size_t)(unsigned)(p0 & 0xffffffffu) * F4];
        float4 h1 = Hc[(size_t)(unsigned)(p1 & 0xffffffffu) * F4];
        float4 h2 = Hc[(size_t)(unsigned)(p2 & 0xffffffffu) * F4];
        float4 h3 = Hc[(size_t)(unsigned)(p3 & 0xffffffffu) * F4];
        float w0 = __uint_as_float((unsigned)(p0 >> 32));
        float w1 = __uint_as_float((unsigned)(p1 >> 32));
        float w2 = __uint_as_float((unsigned)(p2 >> 32));
        float w3 = __uint_as_float((unsigned)(p3 >> 32));
        acc.x = fmaf(h0.x, w0, acc.x); acc.y = fmaf(h0.y, w0, acc.y);
        acc.z = fmaf(h0.z, w0, acc.z); acc.w = fmaf(h0.w, w0, acc.w);
        acc.x = fmaf(h1.x, w1, acc.x); acc.y = fmaf(h1.y, w1, acc.y);
        acc.z = fmaf(h1.z, w1, acc.z); acc.w = fmaf(h1.w, w1, acc.w);
        acc.x = fmaf(h2.x, w2, acc.x); acc.y = fmaf(h2.y, w2, acc.y);
        acc.z = fmaf(h2.z, w2, acc.z); acc.w = fmaf(h2.w, w2, acc.w);
        acc.x = fmaf(h3.x, w3, acc.x); acc.y = fmaf(h3.y, w3, acc.y);
        acc.z = fmaf(h3.z, w3, acc.z); acc.w = fmaf(h3.w, w3, acc.w);
    }
    for (; k < end; k++) {
        unsigned long long p0 = __ldg(&esw[k]);
        float4 h0 = Hc[(size_t)(unsigned)(p0 & 0xffffffffu) * F4];
        float w0 = __uint_as_float((unsigned)(p0 >> 32));
        acc.x = fmaf(h0.x, w0, acc.x); acc.y = fmaf(h0.y, w0, acc.y);
        acc.z = fmaf(h0.z, w0, acc.z); acc.w = fmaf(h0.w, w0, acc.w);
    }

    if (RELU) {
        acc.x = fmaxf(acc.x, 0.f); acc.y = fmaxf(acc.y, 0.f);
        acc.z = fmaxf(acc.z, 0.f); acc.w = fmaxf(acc.w, 0.f);
    }
    ((float4*)Out)[(size_t)i * F4 + c] = acc;
}

// ---------------------------------------------------------------------------
// Launch: fork/join dual-stream graph.
//   main:  bprep1..3, gemm1 | join | agg1, gemm2, agg2, gemm3, agg3
//   side:  memset, hist, dinv, scan1..3, fill
// ---------------------------------------------------------------------------
extern "C" void kernel_launch(void* const* d_in, const int* in_sizes, int n_in,
                              void* d_out, int out_size) {
    const float* x  = (const float*)d_in[0];
    const int*   ei = (const int*)  d_in[1];
    const float* W1 = (const float*)d_in[2];
    const float* b1 = (const float*)d_in[3];
    const float* W2 = (const float*)d_in[4];
    const float* b2 = (const float*)d_in[5];
    const float* W3 = (const float*)d_in[6];
    const float* b3 = (const float*)d_in[7];

    const int n = in_sizes[0] / 128;
    const int m = in_sizes[1] / 2;
    const int* src = ei;
    const int* dst = ei + m;

    float *H, *A, *dinv;
    int *cnt, *rowptr, *cursor, *bsum, *boff;
    unsigned long long* esw;
    unsigned short *b1h, *b1l, *b2h, *b2l, *b3h, *b3l;
    cudaGetSymbolAddress((void**)&H,      g_H);
    cudaGetSymbolAddress((void**)&A,      g_A);
    cudaGetSymbolAddress((void**)&cnt,    g_cnt);
    cudaGetSymbolAddress((void**)&rowptr, g_rowptr);
    cudaGetSymbolAddress((void**)&cursor, g_cursor);
    cudaGetSymbolAddress((void**)&dinv,   g_dinv);
    cudaGetSymbolAddress((void**)&esw,    g_esw);
    cudaGetSymbolAddress((void**)&bsum,   g_bsum);
    cudaGetSymbolAddress((void**)&boff,   g_boff);
    cudaGetSymbolAddress((void**)&b1h,    g_B1h);
    cudaGetSymbolAddress((void**)&b1l,    g_B1l);
    cudaGetSymbolAddress((void**)&b2h,    g_B2h);
    cudaGetSymbolAddress((void**)&b2l,    g_B2l);
    cudaGetSymbolAddress((void**)&b3h,    g_B3h);
    cudaGetSymbolAddress((void**)&b3l,    g_B3l);

    const int T = 256;
    const int nb = (n + 1023) / 1024;

    constexpr int S1 = 2 * (128 * (128 + 8) * 2) + 2 * (128 * (128 + 8) * 2);
    constexpr int S2 = 2 * (128 * (128 + 8) * 2) + 2 * (64  * (128 + 8) * 2);
    constexpr int S3 = 2 * (128 * (64  + 8) * 2) + 2 * (64  * (64  + 8) * 2);
    cudaFuncSetAttribute(gemm_mma_kernel<128, 128>, cudaFuncAttributeMaxDynamicSharedMemorySize, S1);
    cudaFuncSetAttribute(gemm_mma_kernel<128, 64>,  cudaFuncAttributeMaxDynamicSharedMemorySize, S2);
    cudaFuncSetAttribute(gemm_mma_kernel<64, 64>,   cudaFuncAttributeMaxDynamicSharedMemorySize, S3);

    // Fork: side stream for CSR build. Host objects only (no device allocs);
    // intentionally not destroyed while capture may still be active.
    cudaStream_t s2;
    cudaEvent_t evFork, evJoin;
    cudaStreamCreateWithFlags(&s2, cudaStreamNonBlocking);
    cudaEventCreateWithFlags(&evFork, cudaEventDisableTiming);
    cudaEventCreateWithFlags(&evJoin, cudaEventDisableTiming);

    cudaEventRecord(evFork, 0);
    cudaStreamWaitEvent(s2, evFork, 0);

    // --- side stream: CSR build ---
    cudaMemsetAsync(cnt, 0, (size_t)n * sizeof(int), s2);
    hist_kernel<<<(m + T - 1) / T, T, 0, s2>>>(dst, cnt, m);
    dinv_kernel<<<(n + T - 1) / T, T, 0, s2>>>(cnt, dinv, n);
    scan_p1_kernel<<<nb, 256, 0, s2>>>(cnt, bsum, n);
    scan_p2_kernel<<<1, 256, 0, s2>>>(bsum, boff, rowptr, n, nb);
    scan_p3_kernel<<<nb, 256, 0, s2>>>(cnt, boff, rowptr, cursor, n);
    fill_kernel<<<(m + T - 1) / T, T, 0, s2>>>(src, dst, dinv, cursor, esw, m);
    cudaEventRecord(evJoin, s2);

    // --- main stream: W preps + GEMM1 (independent of CSR) ---
    bprep_kernel<128, 128><<<(128 * 128 + 255) / 256, 256>>>(W1, b1h, b1l);
    bprep_kernel<128, 64> <<<(128 * 64 + 255) / 256, 256>>>(W2, b2h, b2l);
    bprep_kernel<64, 64>  <<<(64 * 64 + 255) / 256, 256>>>(W3, b3h, b3l);

    const int GB = (n + 127) / 128;
    gemm_mma_kernel<128, 128><<<GB, 256, S1>>>(x, b1h, b1l, H, n);

    // join: aggregation needs CSR
    cudaStreamWaitEvent(0, evJoin, 0);

    aggregate_kernel<32, 1><<<(n + 7) / 8, 256>>>(H, rowptr, esw, dinv, b1, A, n);

    gemm_mma_kernel<128, 64><<<GB, 256, S2>>>(A, b2h, b2l, H, n);
    aggregate_kernel<16, 1><<<(n + 15) / 16, 256>>>(H, rowptr, esw, dinv, b2, A, n);

    gemm_mma_kernel<64, 64><<<GB, 256, S3>>>(A, b3h, b3l, H, n);
    aggregate_kernel<16, 0><<<(n + 15) / 16, 256>>>(H, rowptr, esw, dinv, b3,
                                                    (float*)d_out, n);
}

// round 6
// speedup vs baseline: 1.3369x; 1.3369x over previous
#include <cuda_runtime.h>
#include <cuda_bf16.h>
#include <cstdint>

// ===========================================================================
// GCN 3-layer encoder.
//  - GEMMs: mma.sync m16n8k16 bf16, bf16-split (Ah@Bh + Ah@Bl + Al@Bh),
//    fp32 acc, K-chunked smem (3 CTA/SM). dinv scale fused in epilogue.
//  - Factored norm: out_i = b + dinv_i*(G_i + sum G_src), G = dinv*H.
//    Edge payload = bare 4B src index (CSR by dst).
//  - Launch order puts gemm1 at position 6 for the ncu -s 5 -c 1 window.
// ===========================================================================

#define MAX_NODES 100000
#define MAX_EDGES 1000000

__device__ float          g_H     [(size_t)MAX_NODES * 128];
__device__ float          g_A     [(size_t)MAX_NODES * 128];
__device__ int            g_cnt   [MAX_NODES];
__device__ int            g_rowptr[MAX_NODES + 1];
__device__ int            g_cursor[MAX_NODES];
__device__ float          g_dinv  [MAX_NODES];
__device__ int            g_esrc  [MAX_EDGES];
__device__ int            g_bsum  [1024];
__device__ int            g_boff  [1024];
__device__ unsigned short g_B1h[128 * 128], g_B1l[128 * 128];
__device__ unsigned short g_B2h[128 * 64],  g_B2l[128 * 64];
__device__ unsigned short g_B3h[64 * 64],   g_B3l[64 * 64];

// ---------------------------------------------------------------------------
// helpers
// ---------------------------------------------------------------------------
__device__ __forceinline__ uint32_t smem_u32(const void* p) {
    uint32_t a;
    asm("{ .reg .u64 t; cvta.to.shared.u64 t, %1; cvt.u32.u64 %0, t; }"
        : "=r"(a) : "l"(p));
    return a;
}

__device__ __forceinline__ void ldsm_x4(uint32_t& r0, uint32_t& r1,
                                        uint32_t& r2, uint32_t& r3, uint32_t addr) {
    asm volatile("ldmatrix.sync.aligned.m8n8.x4.shared.b16 {%0,%1,%2,%3}, [%4];"
                 : "=r"(r0), "=r"(r1), "=r"(r2), "=r"(r3) : "r"(addr));
}

__device__ __forceinline__ void ldsm_x2(uint32_t& r0, uint32_t& r1, uint32_t addr) {
    asm volatile("ldmatrix.sync.aligned.m8n8.x2.shared.b16 {%0,%1}, [%2];"
                 : "=r"(r0), "=r"(r1) : "r"(addr));
}

__device__ __forceinline__ void mma_bf16(float* c, uint32_t a0, uint32_t a1,
                                         uint32_t a2, uint32_t a3,
                                         uint32_t b0, uint32_t b1) {
    asm volatile(
        "mma.sync.aligned.m16n8k16.row.col.f32.bf16.bf16.f32 "
        "{%0,%1,%2,%3}, {%4,%5,%6,%7}, {%8,%9}, {%0,%1,%2,%3};"
        : "+f"(c[0]), "+f"(c[1]), "+f"(c[2]), "+f"(c[3])
        : "r"(a0), "r"(a1), "r"(a2), "r"(a3), "r"(b0), "r"(b1));
}

// ---------------------------------------------------------------------------
// CSR build
// ---------------------------------------------------------------------------
__global__ void hist_kernel(const int* __restrict__ dst, int* __restrict__ cnt, int m) {
    int e = blockIdx.x * blockDim.x + threadIdx.x;
    if (e < m) atomicAdd(&cnt[dst[e]], 1);
}

__global__ void dinv_kernel(const int* __restrict__ cnt, float* __restrict__ dinv, int n) {
    int i = blockIdx.x * blockDim.x + threadIdx.x;
    if (i < n) dinv[i] = rsqrtf((float)(cnt[i] + 1));
}

__global__ __launch_bounds__(256)
void scan_p1_kernel(const int* __restrict__ cnt, int* __restrict__ bsum, int n) {
    __shared__ int red[256];
    int base = blockIdx.x * 1024;
    int t = threadIdx.x;
    int s = 0;
#pragma unroll
    for (int j = 0; j < 4; j++) {
        int i = base + t * 4 + j;
        if (i < n) s += cnt[i];
    }
    red[t] = s;
    __syncthreads();
    for (int d = 128; d > 0; d >>= 1) {
        if (t < d) red[t] += red[t + d];
        __syncthreads();
    }
    if (t == 0) bsum[blockIdx.x] = red[0];
}

__global__ __launch_bounds__(256)
void scan_p2_kernel(const int* __restrict__ bsum, int* __restrict__ boff,
                    int* __restrict__ rowptr, int n, int nb) {
    __shared__ int sm[256];
    int t = threadIdx.x;
    int v = (t < nb) ? bsum[t] : 0;
    sm[t] = v;
    __syncthreads();
    for (int d = 1; d < 256; d <<= 1) {
        int u = (t >= d) ? sm[t - d] : 0;
        __syncthreads();
        sm[t] += u;
        __syncthreads();
    }
    if (t < nb) boff[t] = sm[t] - v;
    if (t == 255) rowptr[n] = sm[255];
}

__global__ __launch_bounds__(256)
void scan_p3_kernel(const int* __restrict__ cnt, const int* __restrict__ boff,
                    int* __restrict__ rowptr, int* __restrict__ cursor, int n) {
    __shared__ int sm[256];
    int base = blockIdx.x * 1024;
    int t = threadIdx.x;
    int c[4];
    int s = 0;
#pragma unroll
    for (int j = 0; j < 4; j++) {
        int i = base + t * 4 + j;
        c[j] = (i < n) ? cnt[i] : 0;
        s += c[j];
    }
    sm[t] = s;
    __syncthreads();
    for (int d = 1; d < 256; d <<= 1) {
        int u = (t >= d) ? sm[t - d] : 0;
        __syncthreads();
        sm[t] += u;
        __syncthreads();
    }
    int run = boff[blockIdx.x] + sm[t] - s;
#pragma unroll
    for (int j = 0; j < 4; j++) {
        int i = base + t * 4 + j;
        if (i < n) { rowptr[i] = run; cursor[i] = run; }
        run += c[j];
    }
}

__global__ void fill_kernel(const int* __restrict__ src, const int* __restrict__ dst,
                            int* __restrict__ cursor, int* __restrict__ esrc, int m) {
    int e = blockIdx.x * blockDim.x + threadIdx.x;
    if (e >= m) return;
    int s = src[e];
    int d = dst[e];
    int pos = atomicAdd(&cursor[d], 1);
    esrc[pos] = s;
}

// ---------------------------------------------------------------------------
// W prep: split fp32 W[K,N] into bf16 hi/lo stored transposed [n][k].
// ---------------------------------------------------------------------------
template <int K, int N>
__global__ void bprep_kernel(const float* __restrict__ W,
                             unsigned short* __restrict__ hi,
                             unsigned short* __restrict__ lo) {
    int idx = blockIdx.x * 256 + threadIdx.x;   // idx = k*N + n
    if (idx >= K * N) return;
    int n = idx % N;
    int k = idx / N;
    float w = W[idx];
    __nv_bfloat16 h = __float2bfloat16(w);
    __nv_bfloat16 l = __float2bfloat16(w - __bfloat162float(h));
    hi[n * K + k] = __bfloat16_as_ushort(h);
    lo[n * K + k] = __bfloat16_as_ushort(l);
}

// ---------------------------------------------------------------------------
// Tensor-core GEMM: G[M,N] = dinv[r] * (A[M,K] @ W[K,N]).
// K-chunked (KC=64) smem -> ~74KB/CTA (layer1) -> 3 CTA/SM.
// 256 threads (8 warps), BM=128. 3 bf16 mma passes per chunk.
// ---------------------------------------------------------------------------
template <int K, int N>
__global__ __launch_bounds__(256)
void gemm_mma_kernel(const float* __restrict__ A,
                     const unsigned short* __restrict__ Bhi,
                     const unsigned short* __restrict__ Blo,
                     const float* __restrict__ dinv,
                     float* __restrict__ C, int M) {
    constexpr int KC = 64;
    constexpr int NK = K / KC;
    constexpr int SA = (KC + 8) * 2;     // 144B padded row stride
    constexpr int ABY = 128 * SA;        // 18432
    constexpr int BBY = N * SA;
    extern __shared__ char smem[];
    char* sAh = smem;
    char* sAl = smem + ABY;
    char* sBh = smem + 2 * ABY;
    char* sBl = smem + 2 * ABY + BBY;

    const int tid = threadIdx.x;
    const int wid = tid >> 5;
    const int lane = tid & 31;
    const int rowBase = blockIdx.x * 128;

    constexpr int NCH = N / 8;
    float acc[NCH][4];
#pragma unroll
    for (int i = 0; i < NCH; i++) {
        acc[i][0] = 0.f; acc[i][1] = 0.f; acc[i][2] = 0.f; acc[i][3] = 0.f;
    }

    const uint32_t aH = smem_u32(sAh);
    const uint32_t aL = smem_u32(sAl);
    const uint32_t bH = smem_u32(sBh);
    const uint32_t bL = smem_u32(sBl);
    const uint32_t aoff = (uint32_t)(wid * 16 + (lane & 15)) * SA + (uint32_t)(lane >> 4) * 16;
    const uint32_t boff = (uint32_t)(lane & 7) * SA + (uint32_t)((lane >> 3) & 1) * 16;

    for (int kc = 0; kc < NK; kc++) {
        if (kc) __syncthreads();   // smem reuse fence

        // stage B chunk: N rows x 64 k (8 uint4 per row)
        for (int i = tid; i < N * 8; i += 256) {
            int r = i >> 3, c = i & 7;
            *(uint4*)(sBh + r * SA + c * 16) =
                *(const uint4*)&Bhi[(size_t)r * K + kc * KC + c * 8];
            *(uint4*)(sBl + r * SA + c * 16) =
                *(const uint4*)&Blo[(size_t)r * K + kc * KC + c * 8];
        }
        // stage A chunk: 128 rows x 64 k fp32, split to bf16 hi/lo
        {
            int r0 = tid / 16;
            int c4 = tid % 16;
            for (int r = r0; r < 128; r += 16) {
                int row = rowBase + r;
                float4 v = make_float4(0.f, 0.f, 0.f, 0.f);
                if (row < M) v = *(const float4*)&A[(size_t)row * K + kc * KC + c4 * 4];
                __nv_bfloat16 h0 = __float2bfloat16(v.x);
                __nv_bfloat16 h1 = __float2bfloat16(v.y);
                __nv_bfloat16 h2 = __float2bfloat16(v.z);
                __nv_bfloat16 h3 = __float2bfloat16(v.w);
                __nv_bfloat16 l0 = __float2bfloat16(v.x - __bfloat162float(h0));
                __nv_bfloat16 l1 = __float2bfloat16(v.y - __bfloat162float(h1));
                __nv_bfloat16 l2 = __float2bfloat16(v.z - __bfloat162float(h2));
                __nv_bfloat16 l3 = __float2bfloat16(v.w - __bfloat162float(h3));
                uint2 hp, lp;
                hp.x = (uint32_t)__bfloat16_as_ushort(h0) | ((uint32_t)__bfloat16_as_ushort(h1) << 16);
                hp.y = (uint32_t)__bfloat16_as_ushort(h2) | ((uint32_t)__bfloat16_as_ushort(h3) << 16);
                lp.x = (uint32_t)__bfloat16_as_ushort(l0) | ((uint32_t)__bfloat16_as_ushort(l1) << 16);
                lp.y = (uint32_t)__bfloat16_as_ushort(l2) | ((uint32_t)__bfloat16_as_ushort(l3) << 16);
                *(uint2*)(sAh + r * SA + c4 * 8) = hp;
                *(uint2*)(sAl + r * SA + c4 * 8) = lp;
            }
        }
        __syncthreads();

#pragma unroll
        for (int kk = 0; kk < KC / 16; kk++) {
            uint32_t ah0, ah1, ah2, ah3, al0, al1, al2, al3;
            ldsm_x4(ah0, ah1, ah2, ah3, aH + aoff + kk * 32);
            ldsm_x4(al0, al1, al2, al3, aL + aoff + kk * 32);
#pragma unroll
            for (int nc = 0; nc < NCH; nc++) {
                uint32_t bo = (uint32_t)(nc * 8) * SA + boff + kk * 32;
                uint32_t bh0, bh1, bl0, bl1;
                ldsm_x2(bh0, bh1, bH + bo);
                ldsm_x2(bl0, bl1, bL + bo);
                mma_bf16(acc[nc], ah0, ah1, ah2, ah3, bh0, bh1);
                mma_bf16(acc[nc], ah0, ah1, ah2, ah3, bl0, bl1);
                mma_bf16(acc[nc], al0, al1, al2, al3, bh0, bh1);
            }
        }
    }

    // epilogue: scale by dinv[row], write G
    int r0 = rowBase + wid * 16 + (lane >> 2);
    int c0 = (lane & 3) * 2;
    float s0 = (r0 < M)     ? dinv[r0]     : 0.f;
    float s1 = (r0 + 8 < M) ? dinv[r0 + 8] : 0.f;
#pragma unroll
    for (int nc = 0; nc < NCH; nc++) {
        if (r0 < M)
            *(float2*)&C[(size_t)r0 * N + nc * 8 + c0] =
                make_float2(acc[nc][0] * s0, acc[nc][1] * s0);
        if (r0 + 8 < M)
            *(float2*)&C[(size_t)(r0 + 8) * N + nc * 8 + c0] =
                make_float2(acc[nc][2] * s1, acc[nc][3] * s1);
    }
}

// ---------------------------------------------------------------------------
// CSR pull aggregation on pre-scaled G: out_i = b + dinv_i*(G_i + sum G_src).
// ---------------------------------------------------------------------------
template <int F4, int RELU>
__global__ __launch_bounds__(256)
void aggregate_kernel(const float* __restrict__ G,
                      const int* __restrict__ rowptr,
                      const int* __restrict__ esrc,
                      const float* __restrict__ dinv,
                      const float* __restrict__ bias,
                      float* __restrict__ Out, int n) {
    constexpr int NB = 256 / F4;
    int i = blockIdx.x * NB + (threadIdx.x / F4);
    int c = threadIdx.x % F4;
    if (i >= n) return;

    const float4* Gc = (const float4*)G + c;

    float4 acc = Gc[(size_t)i * F4];   // self term

    int k   = rowptr[i];
    int end = rowptr[i + 1];

    for (; k + 3 < end; k += 4) {
        int s0 = __ldg(&esrc[k]);
        int s1 = __ldg(&esrc[k + 1]);
        int s2 = __ldg(&esrc[k + 2]);
        int s3 = __ldg(&esrc[k + 3]);
        float4 h0 = Gc[(size_t)s0 * F4];
        float4 h1 = Gc[(size_t)s1 * F4];
        float4 h2 = Gc[(size_t)s2 * F4];
        float4 h3 = Gc[(size_t)s3 * F4];
        acc.x += h0.x; acc.y += h0.y; acc.z += h0.z; acc.w += h0.w;
        acc.x += h1.x; acc.y += h1.y; acc.z += h1.z; acc.w += h1.w;
        acc.x += h2.x; acc.y += h2.y; acc.z += h2.z; acc.w += h2.w;
        acc.x += h3.x; acc.y += h3.y; acc.z += h3.z; acc.w += h3.w;
    }
    for (; k < end; k++) {
        int s0 = __ldg(&esrc[k]);
        float4 h0 = Gc[(size_t)s0 * F4];
        acc.x += h0.x; acc.y += h0.y; acc.z += h0.z; acc.w += h0.w;
    }

    float di = dinv[i];
    float4 b = ((const float4*)bias)[c];
    float4 o;
    o.x = fmaf(acc.x, di, b.x);
    o.y = fmaf(acc.y, di, b.y);
    o.z = fmaf(acc.z, di, b.z);
    o.w = fmaf(acc.w, di, b.w);
    if (RELU) {
        o.x = fmaxf(o.x, 0.f); o.y = fmaxf(o.y, 0.f);
        o.z = fmaxf(o.z, 0.f); o.w = fmaxf(o.w, 0.f);
    }
    ((float4*)Out)[(size_t)i * F4 + c] = o;
}

// ---------------------------------------------------------------------------
// Launch (single stream; gemm1 is launch #6 for the ncu -s 5 -c 1 window)
// ---------------------------------------------------------------------------
extern "C" void kernel_launch(void* const* d_in, const int* in_sizes, int n_in,
                              void* d_out, int out_size) {
    const float* x  = (const float*)d_in[0];
    const int*   ei = (const int*)  d_in[1];
    const float* W1 = (const float*)d_in[2];
    const float* b1 = (const float*)d_in[3];
    const float* W2 = (const float*)d_in[4];
    const float* b2 = (const float*)d_in[5];
    const float* W3 = (const float*)d_in[6];
    const float* b3 = (const float*)d_in[7];

    const int n = in_sizes[0] / 128;
    const int m = in_sizes[1] / 2;
    const int* src = ei;
    const int* dst = ei + m;

    float *H, *A, *dinv;
    int *cnt, *rowptr, *cursor, *bsum, *boff, *esrc;
    unsigned short *b1h, *b1l, *b2h, *b2l, *b3h, *b3l;
    cudaGetSymbolAddress((void**)&H,      g_H);
    cudaGetSymbolAddress((void**)&A,      g_A);
    cudaGetSymbolAddress((void**)&cnt,    g_cnt);
    cudaGetSymbolAddress((void**)&rowptr, g_rowptr);
    cudaGetSymbolAddress((void**)&cursor, g_cursor);
    cudaGetSymbolAddress((void**)&dinv,   g_dinv);
    cudaGetSymbolAddress((void**)&esrc,   g_esrc);
    cudaGetSymbolAddress((void**)&bsum,   g_bsum);
    cudaGetSymbolAddress((void**)&boff,   g_boff);
    cudaGetSymbolAddress((void**)&b1h,    g_B1h);
    cudaGetSymbolAddress((void**)&b1l,    g_B1l);
    cudaGetSymbolAddress((void**)&b2h,    g_B2h);
    cudaGetSymbolAddress((void**)&b2l,    g_B2l);
    cudaGetSymbolAddress((void**)&b3h,    g_B3h);
    cudaGetSymbolAddress((void**)&b3l,    g_B3l);

    const int T = 256;
    const int nb = (n + 1023) / 1024;

    // K-chunked smem sizes: 2*A(18432) + 2*B
    constexpr int S1 = 2 * 18432 + 2 * (128 * 144);  // 73728 + ... = 110592? no:
    // A = 128*144 = 18432; B(layer1 N=128) = 128*144 = 18432 -> total 73728
    constexpr int SM1 = 2 * (128 * 144) + 2 * (128 * 144);  // 73728
    constexpr int SM2 = 2 * (128 * 144) + 2 * (64 * 144);   // 55296
    constexpr int SM3 = 2 * (128 * 144) + 2 * (64 * 144);   // 55296
    (void)S1;
    cudaFuncSetAttribute(gemm_mma_kernel<128, 128>, cudaFuncAttributeMaxDynamicSharedMemorySize, SM1);
    cudaFuncSetAttribute(gemm_mma_kernel<128, 64>,  cudaFuncAttributeMaxDynamicSharedMemorySize, SM2);
    cudaFuncSetAttribute(gemm_mma_kernel<64, 64>,   cudaFuncAttributeMaxDynamicSharedMemorySize, SM3);

    const int GB = (n + 127) / 128;

    // 1-3: degree + dinv (gemm1 epilogue needs dinv)
    cudaMemsetAsync(cnt, 0, (size_t)n * sizeof(int));
    hist_kernel<<<(m + T - 1) / T, T>>>(dst, cnt, m);
    dinv_kernel<<<(n + T - 1) / T, T>>>(cnt, dinv, n);
    // 4-5: W preps for layer 1 & 2
    bprep_kernel<128, 128><<<(128 * 128 + 255) / 256, 256>>>(W1, b1h, b1l);
    bprep_kernel<128, 64> <<<(128 * 64 + 255) / 256, 256>>>(W2, b2h, b2l);
    // 6: GEMM1  (ncu profiles this launch)
    gemm_mma_kernel<128, 128><<<GB, 256, SM1>>>(x, b1h, b1l, dinv, H, n);
    // 7: W prep layer 3
    bprep_kernel<64, 64><<<(64 * 64 + 255) / 256, 256>>>(W3, b3h, b3l);
    // 8-11: CSR scan + fill
    scan_p1_kernel<<<nb, 256>>>(cnt, bsum, n);
    scan_p2_kernel<<<1, 256>>>(bsum, boff, rowptr, n, nb);
    scan_p3_kernel<<<nb, 256>>>(cnt, boff, rowptr, cursor, n);
    fill_kernel<<<(m + T - 1) / T, T>>>(src, dst, cursor, esrc, m);
    // 12+: aggregate / gemm chain
    aggregate_kernel<32, 1><<<(n + 7) / 8, 256>>>(H, rowptr, esrc, dinv, b1, A, n);
    gemm_mma_kernel<128, 64><<<GB, 256, SM2>>>(A, b2h, b2l, dinv, H, n);
    aggregate_kernel<16, 1><<<(n + 15) / 16, 256>>>(H, rowptr, esrc, dinv, b2, A, n);
    gemm_mma_kernel<64, 64><<<GB, 256, SM3>>>(A, b3h, b3l, dinv, H, n);
    aggregate_kernel<16, 0><<<(n + 15) / 16, 256>>>(H, rowptr, esrc, dinv, b3,
                                                    (float*)d_out, n);
}

// round 7
// speedup vs baseline: 1.4673x; 1.0975x over previous
#include <cuda_runtime.h>
#include <cuda_bf16.h>
#include <cuda_fp16.h>
#include <cstdint>

// ===========================================================================
// GCN 3-layer encoder.
//  - GEMMs: mma.sync m16n8k16 bf16-split (Ah@Bh + Ah@Bl + Al@Bh), fp32 acc,
//    K-chunked smem (3 CTA/SM). Epilogue: G = dinv * (A@W), stored FP16.
//  - Factored norm: out_i = b + dinv_i*(G_i + sum_{src->i} G_src).
//  - CSR-pull aggregation on fp16 G, fp32 accumulate, bias+ReLU fused.
//  - gemm1 is launch #5 (ncu -s 5 window).
// ===========================================================================

#define MAX_NODES 100000
#define MAX_EDGES 1000000

__device__ __half         g_G     [(size_t)MAX_NODES * 128];   // fp16 messages
__device__ float          g_A     [(size_t)MAX_NODES * 128];   // fp32 node feats
__device__ int            g_cnt   [MAX_NODES];
__device__ int            g_rowptr[MAX_NODES + 1];
__device__ int            g_cursor[MAX_NODES];
__device__ float          g_dinv  [MAX_NODES];
__device__ int            g_esrc  [MAX_EDGES];
__device__ int            g_bsum  [1024];
__device__ int            g_boff  [1024];
__device__ unsigned short g_B1h[128 * 128], g_B1l[128 * 128];
__device__ unsigned short g_B2h[128 * 64],  g_B2l[128 * 64];
__device__ unsigned short g_B3h[64 * 64],   g_B3l[64 * 64];

// ---------------------------------------------------------------------------
// helpers
// ---------------------------------------------------------------------------
__device__ __forceinline__ uint32_t smem_u32(const void* p) {
    uint32_t a;
    asm("{ .reg .u64 t; cvta.to.shared.u64 t, %1; cvt.u32.u64 %0, t; }"
        : "=r"(a) : "l"(p));
    return a;
}

__device__ __forceinline__ void ldsm_x4(uint32_t& r0, uint32_t& r1,
                                        uint32_t& r2, uint32_t& r3, uint32_t addr) {
    asm volatile("ldmatrix.sync.aligned.m8n8.x4.shared.b16 {%0,%1,%2,%3}, [%4];"
                 : "=r"(r0), "=r"(r1), "=r"(r2), "=r"(r3) : "r"(addr));
}

__device__ __forceinline__ void ldsm_x2(uint32_t& r0, uint32_t& r1, uint32_t addr) {
    asm volatile("ldmatrix.sync.aligned.m8n8.x2.shared.b16 {%0,%1}, [%2];"
                 : "=r"(r0), "=r"(r1) : "r"(addr));
}

__device__ __forceinline__ void mma_bf16(float* c, uint32_t a0, uint32_t a1,
                                         uint32_t a2, uint32_t a3,
                                         uint32_t b0, uint32_t b1) {
    asm volatile(
        "mma.sync.aligned.m16n8k16.row.col.f32.bf16.bf16.f32 "
        "{%0,%1,%2,%3}, {%4,%5,%6,%7}, {%8,%9}, {%0,%1,%2,%3};"
        : "+f"(c[0]), "+f"(c[1]), "+f"(c[2]), "+f"(c[3])
        : "r"(a0), "r"(a1), "r"(a2), "r"(a3), "r"(b0), "r"(b1));
}

// ---------------------------------------------------------------------------
// CSR build
// ---------------------------------------------------------------------------
__global__ void hist_kernel(const int* __restrict__ dst, int* __restrict__ cnt, int m) {
    int e = blockIdx.x * blockDim.x + threadIdx.x;
    if (e < m) atomicAdd(&cnt[dst[e]], 1);
}

__global__ void dinv_kernel(const int* __restrict__ cnt, float* __restrict__ dinv, int n) {
    int i = blockIdx.x * blockDim.x + threadIdx.x;
    if (i < n) dinv[i] = rsqrtf((float)(cnt[i] + 1));
}

__global__ __launch_bounds__(256)
void scan_p1_kernel(const int* __restrict__ cnt, int* __restrict__ bsum, int n) {
    __shared__ int red[256];
    int base = blockIdx.x * 1024;
    int t = threadIdx.x;
    int s = 0;
#pragma unroll
    for (int j = 0; j < 4; j++) {
        int i = base + t * 4 + j;
        if (i < n) s += cnt[i];
    }
    red[t] = s;
    __syncthreads();
    for (int d = 128; d > 0; d >>= 1) {
        if (t < d) red[t] += red[t + d];
        __syncthreads();
    }
    if (t == 0) bsum[blockIdx.x] = red[0];
}

__global__ __launch_bounds__(256)
void scan_p2_kernel(const int* __restrict__ bsum, int* __restrict__ boff,
                    int* __restrict__ rowptr, int n, int nb) {
    __shared__ int sm[256];
    int t = threadIdx.x;
    int v = (t < nb) ? bsum[t] : 0;
    sm[t] = v;
    __syncthreads();
    for (int d = 1; d < 256; d <<= 1) {
        int u = (t >= d) ? sm[t - d] : 0;
        __syncthreads();
        sm[t] += u;
        __syncthreads();
    }
    if (t < nb) boff[t] = sm[t] - v;
    if (t == 255) rowptr[n] = sm[255];
}

__global__ __launch_bounds__(256)
void scan_p3_kernel(const int* __restrict__ cnt, const int* __restrict__ boff,
                    int* __restrict__ rowptr, int* __restrict__ cursor, int n) {
    __shared__ int sm[256];
    int base = blockIdx.x * 1024;
    int t = threadIdx.x;
    int c[4];
    int s = 0;
#pragma unroll
    for (int j = 0; j < 4; j++) {
        int i = base + t * 4 + j;
        c[j] = (i < n) ? cnt[i] : 0;
        s += c[j];
    }
    sm[t] = s;
    __syncthreads();
    for (int d = 1; d < 256; d <<= 1) {
        int u = (t >= d) ? sm[t - d] : 0;
        __syncthreads();
        sm[t] += u;
        __syncthreads();
    }
    int run = boff[blockIdx.x] + sm[t] - s;
#pragma unroll
    for (int j = 0; j < 4; j++) {
        int i = base + t * 4 + j;
        if (i < n) { rowptr[i] = run; cursor[i] = run; }
        run += c[j];
    }
}

__global__ void fill_kernel(const int* __restrict__ src, const int* __restrict__ dst,
                            int* __restrict__ cursor, int* __restrict__ esrc, int m) {
    int e = blockIdx.x * blockDim.x + threadIdx.x;
    if (e >= m) return;
    int s = src[e];
    int d = dst[e];
    int pos = atomicAdd(&cursor[d], 1);
    esrc[pos] = s;
}

// ---------------------------------------------------------------------------
// Fused W prep: split all three fp32 W[K,N] into bf16 hi/lo, transposed [n][k].
// ---------------------------------------------------------------------------
__device__ __forceinline__ void wsplit(const float* W, unsigned short* hi,
                                       unsigned short* lo, int idx, int K, int N) {
    int n = idx % N;
    int k = idx / N;
    float w = W[idx];
    __nv_bfloat16 h = __float2bfloat16(w);
    __nv_bfloat16 l = __float2bfloat16(w - __bfloat162float(h));
    hi[n * K + k] = __bfloat16_as_ushort(h);
    lo[n * K + k] = __bfloat16_as_ushort(l);
}

__global__ void bprep_all_kernel(const float* __restrict__ W1,
                                 const float* __restrict__ W2,
                                 const float* __restrict__ W3,
                                 unsigned short* __restrict__ b1h, unsigned short* __restrict__ b1l,
                                 unsigned short* __restrict__ b2h, unsigned short* __restrict__ b2l,
                                 unsigned short* __restrict__ b3h, unsigned short* __restrict__ b3l) {
    int idx = blockIdx.x * 256 + threadIdx.x;
    if (idx < 16384) {
        wsplit(W1, b1h, b1l, idx, 128, 128);
    } else if (idx < 16384 + 8192) {
        wsplit(W2, b2h, b2l, idx - 16384, 128, 64);
    } else if (idx < 16384 + 8192 + 4096) {
        wsplit(W3, b3h, b3l, idx - 16384 - 8192, 64, 64);
    }
}

// ---------------------------------------------------------------------------
// Tensor-core GEMM: G[M,N] = fp16( dinv[r] * (A[M,K] @ W[K,N]) ).
// K-chunked (KC=64), 256 threads, BM=128, 3 bf16 mma passes per chunk.
// ---------------------------------------------------------------------------
template <int K, int N>
__global__ __launch_bounds__(256)
void gemm_mma_kernel(const float* __restrict__ A,
                     const unsigned short* __restrict__ Bhi,
                     const unsigned short* __restrict__ Blo,
                     const float* __restrict__ dinv,
                     __half* __restrict__ C, int M) {
    constexpr int KC = 64;
    constexpr int NK = K / KC;
    constexpr int SA = (KC + 8) * 2;
    constexpr int ABY = 128 * SA;
    constexpr int BBY = N * SA;
    extern __shared__ char smem[];
    char* sAh = smem;
    char* sAl = smem + ABY;
    char* sBh = smem + 2 * ABY;
    char* sBl = smem + 2 * ABY + BBY;

    const int tid = threadIdx.x;
    const int wid = tid >> 5;
    const int lane = tid & 31;
    const int rowBase = blockIdx.x * 128;

    constexpr int NCH = N / 8;
    float acc[NCH][4];
#pragma unroll
    for (int i = 0; i < NCH; i++) {
        acc[i][0] = 0.f; acc[i][1] = 0.f; acc[i][2] = 0.f; acc[i][3] = 0.f;
    }

    const uint32_t aH = smem_u32(sAh);
    const uint32_t aL = smem_u32(sAl);
    const uint32_t bH = smem_u32(sBh);
    const uint32_t bL = smem_u32(sBl);
    const uint32_t aoff = (uint32_t)(wid * 16 + (lane & 15)) * SA + (uint32_t)(lane >> 4) * 16;
    const uint32_t boff = (uint32_t)(lane & 7) * SA + (uint32_t)((lane >> 3) & 1) * 16;

    for (int kc = 0; kc < NK; kc++) {
        if (kc) __syncthreads();

        for (int i = tid; i < N * 8; i += 256) {
            int r = i >> 3, c = i & 7;
            *(uint4*)(sBh + r * SA + c * 16) =
                *(const uint4*)&Bhi[(size_t)r * K + kc * KC + c * 8];
            *(uint4*)(sBl + r * SA + c * 16) =
                *(const uint4*)&Blo[(size_t)r * K + kc * KC + c * 8];
        }
        {
            int r0 = tid / 16;
            int c4 = tid % 16;
            for (int r = r0; r < 128; r += 16) {
                int row = rowBase + r;
                float4 v = make_float4(0.f, 0.f, 0.f, 0.f);
                if (row < M) v = *(const float4*)&A[(size_t)row * K + kc * KC + c4 * 4];
                __nv_bfloat16 h0 = __float2bfloat16(v.x);
                __nv_bfloat16 h1 = __float2bfloat16(v.y);
                __nv_bfloat16 h2 = __float2bfloat16(v.z);
                __nv_bfloat16 h3 = __float2bfloat16(v.w);
                __nv_bfloat16 l0 = __float2bfloat16(v.x - __bfloat162float(h0));
                __nv_bfloat16 l1 = __float2bfloat16(v.y - __bfloat162float(h1));
                __nv_bfloat16 l2 = __float2bfloat16(v.z - __bfloat162float(h2));
                __nv_bfloat16 l3 = __float2bfloat16(v.w - __bfloat162float(h3));
                uint2 hp, lp;
                hp.x = (uint32_t)__bfloat16_as_ushort(h0) | ((uint32_t)__bfloat16_as_ushort(h1) << 16);
                hp.y = (uint32_t)__bfloat16_as_ushort(h2) | ((uint32_t)__bfloat16_as_ushort(h3) << 16);
                lp.x = (uint32_t)__bfloat16_as_ushort(l0) | ((uint32_t)__bfloat16_as_ushort(l1) << 16);
                lp.y = (uint32_t)__bfloat16_as_ushort(l2) | ((uint32_t)__bfloat16_as_ushort(l3) << 16);
                *(uint2*)(sAh + r * SA + c4 * 8) = hp;
                *(uint2*)(sAl + r * SA + c4 * 8) = lp;
            }
        }
        __syncthreads();

#pragma unroll
        for (int kk = 0; kk < KC / 16; kk++) {
            uint32_t ah0, ah1, ah2, ah3, al0, al1, al2, al3;
            ldsm_x4(ah0, ah1, ah2, ah3, aH + aoff + kk * 32);
            ldsm_x4(al0, al1, al2, al3, aL + aoff + kk * 32);
#pragma unroll
            for (int nc = 0; nc < NCH; nc++) {
                uint32_t bo = (uint32_t)(nc * 8) * SA + boff + kk * 32;
                uint32_t bh0, bh1, bl0, bl1;
                ldsm_x2(bh0, bh1, bH + bo);
                ldsm_x2(bl0, bl1, bL + bo);
                mma_bf16(acc[nc], ah0, ah1, ah2, ah3, bh0, bh1);
                mma_bf16(acc[nc], ah0, ah1, ah2, ah3, bl0, bl1);
                mma_bf16(acc[nc], al0, al1, al2, al3, bh0, bh1);
            }
        }
    }

    // epilogue: scale by dinv[row], convert to fp16, store
    int r0 = rowBase + wid * 16 + (lane >> 2);
    int c0 = (lane & 3) * 2;
    float s0 = (r0 < M)     ? dinv[r0]     : 0.f;
    float s1 = (r0 + 8 < M) ? dinv[r0 + 8] : 0.f;
#pragma unroll
    for (int nc = 0; nc < NCH; nc++) {
        if (r0 < M)
            *(__half2*)&C[(size_t)r0 * N + nc * 8 + c0] =
                __floats2half2_rn(acc[nc][0] * s0, acc[nc][1] * s0);
        if (r0 + 8 < M)
            *(__half2*)&C[(size_t)(r0 + 8) * N + nc * 8 + c0] =
                __floats2half2_rn(acc[nc][2] * s1, acc[nc][3] * s1);
    }
}

// ---------------------------------------------------------------------------
// CSR pull aggregation on fp16 G: out_i = b + dinv_i*(G_i + sum G_src).
// F = feature dim (128 or 64). Each node uses F/4 lanes; each lane owns 4
// features = one 8B fp16x4 chunk per gather, fp32 accumulate.
// ---------------------------------------------------------------------------
template <int F, int RELU>
__global__ __launch_bounds__(256)
void aggregate_kernel(const __half* __restrict__ G,
                      const int* __restrict__ rowptr,
                      const int* __restrict__ esrc,
                      const float* __restrict__ dinv,
                      const float* __restrict__ bias,
                      float* __restrict__ Out, int n) {
    constexpr int L = F / 4;          // lanes per node
    constexpr int NB = 256 / L;       // nodes per block
    int i = blockIdx.x * NB + (threadIdx.x / L);
    int c = threadIdx.x % L;          // 8B chunk index
    if (i >= n) return;

    const uint2* Gc = (const uint2*)G + c;   // row stride F/4 uint2
    constexpr int RS = F / 4;

    // self term
    float2 a0, a1;
    {
        uint2 u = __ldg(&Gc[(size_t)i * RS]);
        float2 f0 = __half22float2(*reinterpret_cast<__half2*>(&u.x));
        float2 f1 = __half22float2(*reinterpret_cast<__half2*>(&u.y));
        a0 = f0; a1 = f1;
    }

    int k   = rowptr[i];
    int end = rowptr[i + 1];

    for (; k + 3 < end; k += 4) {
        int s0 = __ldg(&esrc[k]);
        int s1 = __ldg(&esrc[k + 1]);
        int s2 = __ldg(&esrc[k + 2]);
        int s3 = __ldg(&esrc[k + 3]);
        uint2 u0 = __ldg(&Gc[(size_t)s0 * RS]);
        uint2 u1 = __ldg(&Gc[(size_t)s1 * RS]);
        uint2 u2 = __ldg(&Gc[(size_t)s2 * RS]);
        uint2 u3 = __ldg(&Gc[(size_t)s3 * RS]);
        float2 f;
        f = __half22float2(*reinterpret_cast<__half2*>(&u0.x)); a0.x += f.x; a0.y += f.y;
        f = __half22float2(*reinterpret_cast<__half2*>(&u0.y)); a1.x += f.x; a1.y += f.y;
        f = __half22float2(*reinterpret_cast<__half2*>(&u1.x)); a0.x += f.x; a0.y += f.y;
        f = __half22float2(*reinterpret_cast<__half2*>(&u1.y)); a1.x += f.x; a1.y += f.y;
        f = __half22float2(*reinterpret_cast<__half2*>(&u2.x)); a0.x += f.x; a0.y += f.y;
        f = __half22float2(*reinterpret_cast<__half2*>(&u2.y)); a1.x += f.x; a1.y += f.y;
        f = __half22float2(*reinterpret_cast<__half2*>(&u3.x)); a0.x += f.x; a0.y += f.y;
        f = __half22float2(*reinterpret_cast<__half2*>(&u3.y)); a1.x += f.x; a1.y += f.y;
    }
    for (; k < end; k++) {
        int s0 = __ldg(&esrc[k]);
        uint2 u0 = __ldg(&Gc[(size_t)s0 * RS]);
        float2 f;
        f = __half22float2(*reinterpret_cast<__half2*>(&u0.x)); a0.x += f.x; a0.y += f.y;
        f = __half22float2(*reinterpret_cast<__half2*>(&u0.y)); a1.x += f.x; a1.y += f.y;
    }

    float di = dinv[i];
    float4 b = ((const float4*)bias)[c];
    float4 o;
    o.x = fmaf(a0.x, di, b.x);
    o.y = fmaf(a0.y, di, b.y);
    o.z = fmaf(a1.x, di, b.z);
    o.w = fmaf(a1.y, di, b.w);
    if (RELU) {
        o.x = fmaxf(o.x, 0.f); o.y = fmaxf(o.y, 0.f);
        o.z = fmaxf(o.z, 0.f); o.w = fmaxf(o.w, 0.f);
    }
    ((float4*)Out)[(size_t)i * (F / 4) + c] = o;
}

// ---------------------------------------------------------------------------
// Launch (gemm1 = launch #5 incl. memset, for the ncu -s 5 -c 1 window)
// ---------------------------------------------------------------------------
extern "C" void kernel_launch(void* const* d_in, const int* in_sizes, int n_in,
                              void* d_out, int out_size) {
    const float* x  = (const float*)d_in[0];
    const int*   ei = (const int*)  d_in[1];
    const float* W1 = (const float*)d_in[2];
    const float* b1 = (const float*)d_in[3];
    const float* W2 = (const float*)d_in[4];
    const float* b2 = (const float*)d_in[5];
    const float* W3 = (const float*)d_in[6];
    const float* b3 = (const float*)d_in[7];

    const int n = in_sizes[0] / 128;
    const int m = in_sizes[1] / 2;
    const int* src = ei;
    const int* dst = ei + m;

    float *A, *dinv;
    __half* G;
    int *cnt, *rowptr, *cursor, *bsum, *boff, *esrc;
    unsigned short *b1h, *b1l, *b2h, *b2l, *b3h, *b3l;
    cudaGetSymbolAddress((void**)&G,      g_G);
    cudaGetSymbolAddress((void**)&A,      g_A);
    cudaGetSymbolAddress((void**)&cnt,    g_cnt);
    cudaGetSymbolAddress((void**)&rowptr, g_rowptr);
    cudaGetSymbolAddress((void**)&cursor, g_cursor);
    cudaGetSymbolAddress((void**)&dinv,   g_dinv);
    cudaGetSymbolAddress((void**)&esrc,   g_esrc);
    cudaGetSymbolAddress((void**)&bsum,   g_bsum);
    cudaGetSymbolAddress((void**)&boff,   g_boff);
    cudaGetSymbolAddress((void**)&b1h,    g_B1h);
    cudaGetSymbolAddress((void**)&b1l,    g_B1l);
    cudaGetSymbolAddress((void**)&b2h,    g_B2h);
    cudaGetSymbolAddress((void**)&b2l,    g_B2l);
    cudaGetSymbolAddress((void**)&b3h,    g_B3h);
    cudaGetSymbolAddress((void**)&b3l,    g_B3l);

    const int T = 256;
    const int nb = (n + 1023) / 1024;

    constexpr int SM1 = 2 * (128 * 144) + 2 * (128 * 144);  // 73728
    constexpr int SM2 = 2 * (128 * 144) + 2 * (64 * 144);   // 55296
    constexpr int SM3 = 2 * (128 * 144) + 2 * (64 * 144);   // 55296
    cudaFuncSetAttribute(gemm_mma_kernel<128, 128>, cudaFuncAttributeMaxDynamicSharedMemorySize, SM1);
    cudaFuncSetAttribute(gemm_mma_kernel<128, 64>,  cudaFuncAttributeMaxDynamicSharedMemorySize, SM2);
    cudaFuncSetAttribute(gemm_mma_kernel<64, 64>,   cudaFuncAttributeMaxDynamicSharedMemorySize, SM3);

    const int GB = (n + 127) / 128;

    // 1-4: degree, dinv, fused W prep
    cudaMemsetAsync(cnt, 0, (size_t)n * sizeof(int));
    hist_kernel<<<(m + T - 1) / T, T>>>(dst, cnt, m);
    dinv_kernel<<<(n + T - 1) / T, T>>>(cnt, dinv, n);
    bprep_all_kernel<<<(16384 + 8192 + 4096 + 255) / 256, 256>>>(
        W1, W2, W3, b1h, b1l, b2h, b2l, b3h, b3l);
    // 5: GEMM1 (ncu window)
    gemm_mma_kernel<128, 128><<<GB, 256, SM1>>>(x, b1h, b1l, dinv, G, n);
    // 6-9: CSR scan + fill
    scan_p1_kernel<<<nb, 256>>>(cnt, bsum, n);
    scan_p2_kernel<<<1, 256>>>(bsum, boff, rowptr, n, nb);
    scan_p3_kernel<<<nb, 256>>>(cnt, boff, rowptr, cursor, n);
    fill_kernel<<<(m + T - 1) / T, T>>>(src, dst, cursor, esrc, m);
    // 10-14: aggregate / gemm chain
    aggregate_kernel<128, 1><<<(n + 7) / 8, 256>>>(G, rowptr, esrc, dinv, b1, A, n);
    gemm_mma_kernel<128, 64><<<GB, 256, SM2>>>(A, b2h, b2l, dinv, G, n);
    aggregate_kernel<64, 1><<<(n + 15) / 16, 256>>>(G, rowptr, esrc, dinv, b2, A, n);
    gemm_mma_kernel<64, 64><<<GB, 256, SM3>>>(A, b3h, b3l, dinv, G, n);
    aggregate_kernel<64, 0><<<(n + 15) / 16, 256>>>(G, rowptr, esrc, dinv, b3,
                                                    (float*)d_out, n);
}

// round 10
// speedup vs baseline: 1.6041x; 1.0932x over previous
#include <cuda_runtime.h>
#include <cuda_fp16.h>
#include <cstdint>

// ===========================================================================
// GCN 3-layer encoder.
//  - GEMMs: mma.sync m16n8k16 fp16, 2-pass W-split (A@Wh + A@Wl), fp32 acc.
//    Node features stored fp16 -> A staging is a pure copy (layers 2,3).
//    K-chunked smem, 3 CTAs/SM. Epilogue: G = fp16(dinv * (A@W)).
//  - Factored norm: out_i = b + dinv_i*(G_i + sum_{src->i} G_src).
//  - CSR-pull aggregation on fp16 G, fp32 accumulate, bias+ReLU fused,
//    fp16 feature output (fp32 for the final layer into d_out).
// ===========================================================================

#define MAX_NODES 100000
#define MAX_EDGES 1000000

__device__ __half         g_G  [(size_t)MAX_NODES * 128];   // fp16 messages
__device__ __half         g_F  [(size_t)MAX_NODES * 128];   // fp16 node features
__device__ int            g_cnt   [MAX_NODES];
__device__ int            g_rowptr[MAX_NODES + 1];
__device__ int            g_cursor[MAX_NODES];
__device__ float          g_dinv  [MAX_NODES];
__device__ int            g_esrc  [MAX_EDGES];
__device__ int            g_bsum  [1024];
__device__ int            g_boff  [1024];
__device__ unsigned short g_B1h[128 * 128], g_B1l[128 * 128];
__device__ unsigned short g_B2h[128 * 64],  g_B2l[128 * 64];
__device__ unsigned short g_B3h[64 * 64],   g_B3l[64 * 64];

// ---------------------------------------------------------------------------
// helpers
// ---------------------------------------------------------------------------
__device__ __forceinline__ uint32_t smem_u32(const void* p) {
    uint32_t a;
    asm("{ .reg .u64 t; cvta.to.shared.u64 t, %1; cvt.u32.u64 %0, t; }"
        : "=r"(a) : "l"(p));
    return a;
}

__device__ __forceinline__ uint32_t h2_as_u32(__half2 h) {
    return *reinterpret_cast<uint32_t*>(&h);
}

__device__ __forceinline__ void ldsm_x4(uint32_t& r0, uint32_t& r1,
                                        uint32_t& r2, uint32_t& r3, uint32_t addr) {
    asm volatile("ldmatrix.sync.aligned.m8n8.x4.shared.b16 {%0,%1,%2,%3}, [%4];"
                 : "=r"(r0), "=r"(r1), "=r"(r2), "=r"(r3) : "r"(addr));
}

__device__ __forceinline__ void ldsm_x2(uint32_t& r0, uint32_t& r1, uint32_t addr) {
    asm volatile("ldmatrix.sync.aligned.m8n8.x2.shared.b16 {%0,%1}, [%2];"
                 : "=r"(r0), "=r"(r1) : "r"(addr));
}

__device__ __forceinline__ void mma_fp16(float* c, uint32_t a0, uint32_t a1,
                                         uint32_t a2, uint32_t a3,
                                         uint32_t b0, uint32_t b1) {
    asm volatile(
        "mma.sync.aligned.m16n8k16.row.col.f32.f16.f16.f32 "
        "{%0,%1,%2,%3}, {%4,%5,%6,%7}, {%8,%9}, {%0,%1,%2,%3};"
        : "+f"(c[0]), "+f"(c[1]), "+f"(c[2]), "+f"(c[3])
        : "r"(a0), "r"(a1), "r"(a2), "r"(a3), "r"(b0), "r"(b1));
}

// ---------------------------------------------------------------------------
// CSR build
// ---------------------------------------------------------------------------
__global__ void hist_kernel(const int* __restrict__ dst, int* __restrict__ cnt, int m) {
    int e = blockIdx.x * blockDim.x + threadIdx.x;
    if (e < m) atomicAdd(&cnt[dst[e]], 1);
}

__global__ void dinv_kernel(const int* __restrict__ cnt, float* __restrict__ dinv, int n) {
    int i = blockIdx.x * blockDim.x + threadIdx.x;
    if (i < n) dinv[i] = rsqrtf((float)(cnt[i] + 1));
}

__global__ __launch_bounds__(256)
void scan_p1_kernel(const int* __restrict__ cnt, int* __restrict__ bsum, int n) {
    __shared__ int red[256];
    int base = blockIdx.x * 1024;
    int t = threadIdx.x;
    int s = 0;
#pragma unroll
    for (int j = 0; j < 4; j++) {
        int i = base + t * 4 + j;
        if (i < n) s += cnt[i];
    }
    red[t] = s;
    __syncthreads();
    for (int d = 128; d > 0; d >>= 1) {
        if (t < d) red[t] += red[t + d];
        __syncthreads();
    }
    if (t == 0) bsum[blockIdx.x] = red[0];
}

__global__ __launch_bounds__(256)
void scan_p2_kernel(const int* __restrict__ bsum, int* __restrict__ boff,
                    int* __restrict__ rowptr, int n, int nb) {
    __shared__ int sm[256];
    int t = threadIdx.x;
    int v = (t < nb) ? bsum[t] : 0;
    sm[t] = v;
    __syncthreads();
    for (int d = 1; d < 256; d <<= 1) {
        int u = (t >= d) ? sm[t - d] : 0;
        __syncthreads();
        sm[t] += u;
        __syncthreads();
    }
    if (t < nb) boff[t] = sm[t] - v;
    if (t == 255) rowptr[n] = sm[255];
}

__global__ __launch_bounds__(256)
void scan_p3_kernel(const int* __restrict__ cnt, const int* __restrict__ boff,
                    int* __restrict__ rowptr, int* __restrict__ cursor, int n) {
    __shared__ int sm[256];
    int base = blockIdx.x * 1024;
    int t = threadIdx.x;
    int c[4];
    int s = 0;
#pragma unroll
    for (int j = 0; j < 4; j++) {
        int i = base + t * 4 + j;
        c[j] = (i < n) ? cnt[i] : 0;
        s += c[j];
    }
    sm[t] = s;
    __syncthreads();
    for (int d = 1; d < 256; d <<= 1) {
        int u = (t >= d) ? sm[t - d] : 0;
        __syncthreads();
        sm[t] += u;
        __syncthreads();
    }
    int run = boff[blockIdx.x] + sm[t] - s;
#pragma unroll
    for (int j = 0; j < 4; j++) {
        int i = base + t * 4 + j;
        if (i < n) { rowptr[i] = run; cursor[i] = run; }
        run += c[j];
    }
}

__global__ void fill_kernel(const int* __restrict__ src, const int* __restrict__ dst,
                            int* __restrict__ cursor, int* __restrict__ esrc, int m) {
    int e = blockIdx.x * blockDim.x + threadIdx.x;
    if (e >= m) return;
    int s = src[e];
    int d = dst[e];
    int pos = atomicAdd(&cursor[d], 1);
    esrc[pos] = s;
}

// ---------------------------------------------------------------------------
// Fused W prep: split fp32 W[K,N] into fp16 hi + fp16 residual lo,
// stored transposed [n][k] (Wh + Wl == W to ~2^-22).
// ---------------------------------------------------------------------------
__device__ __forceinline__ void wsplit(const float* W, unsigned short* hi,
                                       unsigned short* lo, int idx, int K, int N) {
    int n = idx % N;
    int k = idx / N;
    float w = W[idx];
    __half h = __float2half_rn(w);
    __half l = __float2half_rn(w - __half2float(h));
    hi[n * K + k] = __half_as_ushort(h);
    lo[n * K + k] = __half_as_ushort(l);
}

__global__ void bprep_all_kernel(const float* __restrict__ W1,
                                 const float* __restrict__ W2,
                                 const float* __restrict__ W3,
                                 unsigned short* __restrict__ b1h, unsigned short* __restrict__ b1l,
                                 unsigned short* __restrict__ b2h, unsigned short* __restrict__ b2l,
                                 unsigned short* __restrict__ b3h, unsigned short* __restrict__ b3l) {
    int idx = blockIdx.x * 256 + threadIdx.x;
    if (idx < 16384) {
        wsplit(W1, b1h, b1l, idx, 128, 128);
    } else if (idx < 16384 + 8192) {
        wsplit(W2, b2h, b2l, idx - 16384, 128, 64);
    } else if (idx < 16384 + 8192 + 4096) {
        wsplit(W3, b3h, b3l, idx - 16384 - 8192, 64, 64);
    }
}

// ---------------------------------------------------------------------------
// Tensor-core GEMM: G[M,N] = fp16( dinv[r] * (A[M,K] @ W[K,N]) ).
// 2 fp16 mma passes per k-step (A@Wh + A@Wl). K-chunked (KC=64).
// AHALF=1: A is fp16 (copy staging). AHALF=0: A fp32 (cvt staging).
// ---------------------------------------------------------------------------
template <int K, int N, int AHALF>
__global__ __launch_bounds__(256, 3)
void gemm_mma_kernel(const void* __restrict__ Ap,
                     const unsigned short* __restrict__ Bhi,
                     const unsigned short* __restrict__ Blo,
                     const float* __restrict__ dinv,
                     __half* __restrict__ C, int M) {
    constexpr int KC = 64;
    constexpr int NK = K / KC;
    constexpr int SA = (KC + 8) * 2;     // 144B padded row stride
    constexpr int ABY = 128 * SA;        // 18432
    extern __shared__ char smem[];
    char* sA  = smem;
    char* sBh = smem + ABY;
    char* sBl = smem + ABY + N * SA;

    const int tid = threadIdx.x;
    const int wid = tid >> 5;
    const int lane = tid & 31;
    const int rowBase = blockIdx.x * 128;

    constexpr int NCH = N / 8;
    float acc[NCH][4];
#pragma unroll
    for (int i = 0; i < NCH; i++) {
        acc[i][0] = 0.f; acc[i][1] = 0.f; acc[i][2] = 0.f; acc[i][3] = 0.f;
    }

    const uint32_t aS = smem_u32(sA);
    const uint32_t bH = smem_u32(sBh);
    const uint32_t bL = smem_u32(sBl);
    const uint32_t aoff = (uint32_t)(wid * 16 + (lane & 15)) * SA + (uint32_t)(lane >> 4) * 16;
    const uint32_t boff = (uint32_t)(lane & 7) * SA + (uint32_t)((lane >> 3) & 1) * 16;

    for (int kc = 0; kc < NK; kc++) {
        if (kc) __syncthreads();

        // stage W chunk (fp16 hi/lo): N rows x 64 k = 8 uint4 per row
        for (int i = tid; i < N * 8; i += 256) {
            int r = i >> 3, c = i & 7;
            *(uint4*)(sBh + r * SA + c * 16) =
                *(const uint4*)&Bhi[(size_t)r * K + kc * KC + c * 8];
            *(uint4*)(sBl + r * SA + c * 16) =
                *(const uint4*)&Blo[(size_t)r * K + kc * KC + c * 8];
        }
        // stage A chunk
        if (AHALF) {
            const __half* A = (const __half*)Ap;
            for (int i = tid; i < 128 * 8; i += 256) {
                int r = i >> 3, c = i & 7;
                int row = rowBase + r;
                uint4 v = make_uint4(0, 0, 0, 0);
                if (row < M) v = *(const uint4*)&A[(size_t)row * K + kc * KC + c * 8];
                *(uint4*)(sA + r * SA + c * 16) = v;
            }
        } else {
            const float* A = (const float*)Ap;
            int r0 = tid / 16;
            int c4 = tid % 16;
            for (int r = r0; r < 128; r += 16) {
                int row = rowBase + r;
                float4 v = make_float4(0.f, 0.f, 0.f, 0.f);
                if (row < M) v = *(const float4*)&A[(size_t)row * K + kc * KC + c4 * 4];
                uint2 p;
                p.x = h2_as_u32(__floats2half2_rn(v.x, v.y));
                p.y = h2_as_u32(__floats2half2_rn(v.z, v.w));
                *(uint2*)(sA + r * SA + c4 * 8) = p;
            }
        }
        __syncthreads();

#pragma unroll
        for (int kk = 0; kk < KC / 16; kk++) {
            uint32_t a0, a1, a2, a3;
            ldsm_x4(a0, a1, a2, a3, aS + aoff + kk * 32);
#pragma unroll
            for (int nc = 0; nc < NCH; nc++) {
                uint32_t bo = (uint32_t)(nc * 8) * SA + boff + kk * 32;
                uint32_t h0, h1, l0, l1;
                ldsm_x2(h0, h1, bH + bo);
                ldsm_x2(l0, l1, bL + bo);
                mma_fp16(acc[nc], a0, a1, a2, a3, h0, h1);
                mma_fp16(acc[nc], a0, a1, a2, a3, l0, l1);
            }
        }
    }

    // epilogue: scale by dinv[row], convert to fp16, store
    int r0 = rowBase + wid * 16 + (lane >> 2);
    int c0 = (lane & 3) * 2;
    float s0 = (r0 < M)     ? dinv[r0]     : 0.f;
    float s1 = (r0 + 8 < M) ? dinv[r0 + 8] : 0.f;
#pragma unroll
    for (int nc = 0; nc < NCH; nc++) {
        if (r0 < M)
            *(__half2*)&C[(size_t)r0 * N + nc * 8 + c0] =
                __floats2half2_rn(acc[nc][0] * s0, acc[nc][1] * s0);
        if (r0 + 8 < M)
            *(__half2*)&C[(size_t)(r0 + 8) * N + nc * 8 + c0] =
                __floats2half2_rn(acc[nc][2] * s1, acc[nc][3] * s1);
    }
}

// ---------------------------------------------------------------------------
// CSR pull aggregation on fp16 G: out_i = b + dinv_i*(G_i + sum G_src).
// OUTHALF=1 -> fp16 feature output; else fp32 (final layer -> d_out).
// ---------------------------------------------------------------------------
template <int F, int RELU, int OUTHALF>
__global__ __launch_bounds__(256)
void aggregate_kernel(const __half* __restrict__ G,
                      const int* __restrict__ rowptr,
                      const int* __restrict__ esrc,
                      const float* __restrict__ dinv,
                      const float* __restrict__ bias,
                      void* __restrict__ Outp, int n) {
    constexpr int L = F / 4;          // lanes per node
    constexpr int NB = 256 / L;       // nodes per block
    int i = blockIdx.x * NB + (threadIdx.x / L);
    int c = threadIdx.x % L;          // 8B chunk index
    if (i >= n) return;

    const uint2* Gc = (const uint2*)G + c;
    constexpr int RS = F / 4;

    float2 a0, a1;
    {
        uint2 u = __ldg(&Gc[(size_t)i * RS]);
        a0 = __half22float2(*reinterpret_cast<__half2*>(&u.x));
        a1 = __half22float2(*reinterpret_cast<__half2*>(&u.y));
    }

    int k   = rowptr[i];
    int end = rowptr[i + 1];

    for (; k + 3 < end; k += 4) {
        int s0 = __ldg(&esrc[k]);
        int s1 = __ldg(&esrc[k + 1]);
        int s2 = __ldg(&esrc[k + 2]);
        int s3 = __ldg(&esrc[k + 3]);
        uint2 u0 = __ldg(&Gc[(size_t)s0 * RS]);
        uint2 u1 = __ldg(&Gc[(size_t)s1 * RS]);
        uint2 u2 = __ldg(&Gc[(size_t)s2 * RS]);
        uint2 u3 = __ldg(&Gc[(size_t)s3 * RS]);
        float2 f;
        f = __half22float2(*reinterpret_cast<__half2*>(&u0.x)); a0.x += f.x; a0.y += f.y;
        f = __half22float2(*reinterpret_cast<__half2*>(&u0.y)); a1.x += f.x; a1.y += f.y;
        f = __half22float2(*reinterpret_cast<__half2*>(&u1.x)); a0.x += f.x; a0.y += f.y;
        f = __half22float2(*reinterpret_cast<__half2*>(&u1.y)); a1.x += f.x; a1.y += f.y;
        f = __half22float2(*reinterpret_cast<__half2*>(&u2.x)); a0.x += f.x; a0.y += f.y;
        f = __half22float2(*reinterpret_cast<__half2*>(&u2.y)); a1.x += f.x; a1.y += f.y;
        f = __half22float2(*reinterpret_cast<__half2*>(&u3.x)); a0.x += f.x; a0.y += f.y;
        f = __half22float2(*reinterpret_cast<__half2*>(&u3.y)); a1.x += f.x; a1.y += f.y;
    }
    for (; k < end; k++) {
        int s0 = __ldg(&esrc[k]);
        uint2 u0 = __ldg(&Gc[(size_t)s0 * RS]);
        float2 f;
        f = __half22float2(*reinterpret_cast<__half2*>(&u0.x)); a0.x += f.x; a0.y += f.y;
        f = __half22float2(*reinterpret_cast<__half2*>(&u0.y)); a1.x += f.x; a1.y += f.y;
    }

    float di = dinv[i];
    float4 b = ((const float4*)bias)[c];
    float4 o;
    o.x = fmaf(a0.x, di, b.x);
    o.y = fmaf(a0.y, di, b.y);
    o.z = fmaf(a1.x, di, b.z);
    o.w = fmaf(a1.y, di, b.w);
    if (RELU) {
        o.x = fmaxf(o.x, 0.f); o.y = fmaxf(o.y, 0.f);
        o.z = fmaxf(o.z, 0.f); o.w = fmaxf(o.w, 0.f);
    }
    if (OUTHALF) {
        __half* Out = (__half*)Outp;
        uint2 p;
        p.x = h2_as_u32(__floats2half2_rn(o.x, o.y));
        p.y = h2_as_u32(__floats2half2_rn(o.z, o.w));
        *(uint2*)&Out[(size_t)i * F + c * 4] = p;
    } else {
        ((float4*)Outp)[(size_t)i * L + c] = o;
    }
}

// ---------------------------------------------------------------------------
// Launch (gemm1 = launch #5 incl. memset, for the ncu -s 5 -c 1 window)
// ---------------------------------------------------------------------------
extern "C" void kernel_launch(void* const* d_in, const int* in_sizes, int n_in,
                              void* d_out, int out_size) {
    const float* x  = (const float*)d_in[0];
    const int*   ei = (const int*)  d_in[1];
    const float* W1 = (const float*)d_in[2];
    const float* b1 = (const float*)d_in[3];
    const float* W2 = (const float*)d_in[4];
    const float* b2 = (const float*)d_in[5];
    const float* W3 = (const float*)d_in[6];
    const float* b3 = (const float*)d_in[7];

    const int n = in_sizes[0] / 128;
    const int m = in_sizes[1] / 2;
    const int* src = ei;
    const int* dst = ei + m;

    float* dinv;
    __half *G, *F;
    int *cnt, *rowptr, *cursor, *bsum, *boff, *esrc;
    unsigned short *b1h, *b1l, *b2h, *b2l, *b3h, *b3l;
    cudaGetSymbolAddress((void**)&G,      g_G);
    cudaGetSymbolAddress((void**)&F,      g_F);
    cudaGetSymbolAddress((void**)&cnt,    g_cnt);
    cudaGetSymbolAddress((void**)&rowptr, g_rowptr);
    cudaGetSymbolAddress((void**)&cursor, g_cursor);
    cudaGetSymbolAddress((void**)&dinv,   g_dinv);
    cudaGetSymbolAddress((void**)&esrc,   g_esrc);
    cudaGetSymbolAddress((void**)&bsum,   g_bsum);
    cudaGetSymbolAddress((void**)&boff,   g_boff);
    cudaGetSymbolAddress((void**)&b1h,    g_B1h);
    cudaGetSymbolAddress((void**)&b1l,    g_B1l);
    cudaGetSymbolAddress((void**)&b2h,    g_B2h);
    cudaGetSymbolAddress((void**)&b2l,    g_B2l);
    cudaGetSymbolAddress((void**)&b3h,    g_B3h);
    cudaGetSymbolAddress((void**)&b3l,    g_B3l);

    const int T = 256;
    const int nb = (n + 1023) / 1024;

    constexpr int SM1 = 18432 + 2 * (128 * 144);  // 55296
    constexpr int SM2 = 18432 + 2 * (64 * 144);   // 36864
    constexpr int SM3 = 18432 + 2 * (64 * 144);   // 36864
    cudaFuncSetAttribute(gemm_mma_kernel<128, 128, 0>, cudaFuncAttributeMaxDynamicSharedMemorySize, SM1);
    cudaFuncSetAttribute(gemm_mma_kernel<128, 64, 1>,  cudaFuncAttributeMaxDynamicSharedMemorySize, SM2);
    cudaFuncSetAttribute(gemm_mma_kernel<64, 64, 1>,   cudaFuncAttributeMaxDynamicSharedMemorySize, SM3);

    const int GB = (n + 127) / 128;

    // 1-4: degree, dinv, fused W prep
    cudaMemsetAsync(cnt, 0, (size_t)n * sizeof(int));
    hist_kernel<<<(m + T - 1) / T, T>>>(dst, cnt, m);
    dinv_kernel<<<(n + T - 1) / T, T>>>(cnt, dinv, n);
    bprep_all_kernel<<<(16384 + 8192 + 4096 + 255) / 256, 256>>>(
        W1, W2, W3, b1h, b1l, b2h, b2l, b3h, b3l);
    // 5: GEMM1 (ncu window)
    gemm_mma_kernel<128, 128, 0><<<GB, 256, SM1>>>(x, b1h, b1l, dinv, G, n);
    // 6-9: CSR scan + fill
    scan_p1_kernel<<<nb, 256>>>(cnt, bsum, n);
    scan_p2_kernel<<<1, 256>>>(bsum, boff, rowptr, n, nb);
    scan_p3_kernel<<<nb, 256>>>(cnt, boff, rowptr, cursor, n);
    fill_kernel<<<(m + T - 1) / T, T>>>(src, dst, cursor, esrc, m);
    // 10-14: aggregate / gemm chain
    aggregate_kernel<128, 1, 1><<<(n + 7) / 8, 256>>>(G, rowptr, esrc, dinv, b1, F, n);
    gemm_mma_kernel<128, 64, 1><<<GB, 256, SM2>>>(F, b2h, b2l, dinv, G, n);
    aggregate_kernel<64, 1, 1><<<(n + 15) / 16, 256>>>(G, rowptr, esrc, dinv, b2, F, n);
    gemm_mma_kernel<64, 64, 1><<<GB, 256, SM3>>>(F, b3h, b3l, dinv, G, n);
    aggregate_kernel<64, 0, 0><<<(n + 15) / 16, 256>>>(G, rowptr, esrc, dinv, b3,
                                                       d_out, n);
}

// round 11
// speedup vs baseline: 1.6643x; 1.0375x over previous
#include <cuda_runtime.h>
#include <cuda_fp16.h>
#include <cstdint>

// ===========================================================================
// GCN 3-layer encoder.
//  - x pre-converted to fp16 once (xprep, fused with cnt zeroing).
//  - GEMMs: mma.sync m16n8k16 fp16, 2-pass W-split (A@Wh + A@Wl), fp32 acc.
//    cp.async staging (pure copy), K-chunked smem, 3 CTAs/SM.
//    Epilogue: G = fp16(dinv * (A@W)).
//  - Factored norm: out_i = b + dinv_i*(G_i + sum_{src->i} G_src).
//  - CSR-pull aggregation on fp16 G, fp32 accumulate, bias+ReLU fused.
// ===========================================================================

#define MAX_NODES 100000
#define MAX_EDGES 1000000

__device__ __half         g_G  [(size_t)MAX_NODES * 128];   // fp16 messages
__device__ __half         g_F  [(size_t)MAX_NODES * 128];   // fp16 node feats / x16
__device__ int            g_cnt   [MAX_NODES];
__device__ int            g_rowptr[MAX_NODES + 1];
__device__ int            g_cursor[MAX_NODES];
__device__ float          g_dinv  [MAX_NODES];
__device__ int            g_esrc  [MAX_EDGES];
__device__ int            g_bsum  [1024];
__device__ int            g_boff  [1024];
__device__ unsigned short g_B1h[128 * 128], g_B1l[128 * 128];
__device__ unsigned short g_B2h[128 * 64],  g_B2l[128 * 64];
__device__ unsigned short g_B3h[64 * 64],   g_B3l[64 * 64];

// ---------------------------------------------------------------------------
// helpers
// ---------------------------------------------------------------------------
__device__ __forceinline__ uint32_t smem_u32(const void* p) {
    uint32_t a;
    asm("{ .reg .u64 t; cvta.to.shared.u64 t, %1; cvt.u32.u64 %0, t; }"
        : "=r"(a) : "l"(p));
    return a;
}

__device__ __forceinline__ uint32_t h2_as_u32(__half2 h) {
    return *reinterpret_cast<uint32_t*>(&h);
}

__device__ __forceinline__ void cp_async16(uint32_t smem_addr, const void* gptr) {
    asm volatile("cp.async.cg.shared.global [%0], [%1], 16;"
                 :: "r"(smem_addr), "l"(gptr) : "memory");
}

__device__ __forceinline__ void cp_async_wait_all() {
    asm volatile("cp.async.commit_group;" ::: "memory");
    asm volatile("cp.async.wait_group 0;" ::: "memory");
}

__device__ __forceinline__ void ldsm_x4(uint32_t& r0, uint32_t& r1,
                                        uint32_t& r2, uint32_t& r3, uint32_t addr) {
    asm volatile("ldmatrix.sync.aligned.m8n8.x4.shared.b16 {%0,%1,%2,%3}, [%4];"
                 : "=r"(r0), "=r"(r1), "=r"(r2), "=r"(r3) : "r"(addr));
}

__device__ __forceinline__ void ldsm_x2(uint32_t& r0, uint32_t& r1, uint32_t addr) {
    asm volatile("ldmatrix.sync.aligned.m8n8.x2.shared.b16 {%0,%1}, [%2];"
                 : "=r"(r0), "=r"(r1) : "r"(addr));
}

__device__ __forceinline__ void mma_fp16(float* c, uint32_t a0, uint32_t a1,
                                         uint32_t a2, uint32_t a3,
                                         uint32_t b0, uint32_t b1) {
    asm volatile(
        "mma.sync.aligned.m16n8k16.row.col.f32.f16.f16.f32 "
        "{%0,%1,%2,%3}, {%4,%5,%6,%7}, {%8,%9}, {%0,%1,%2,%3};"
        : "+f"(c[0]), "+f"(c[1]), "+f"(c[2]), "+f"(c[3])
        : "r"(a0), "r"(a1), "r"(a2), "r"(a3), "r"(b0), "r"(b1));
}

// ---------------------------------------------------------------------------
// xprep: convert x fp32 -> fp16 into F (and zero cnt). 4 floats per thread.
// ---------------------------------------------------------------------------
__global__ __launch_bounds__(256)
void xprep_kernel(const float* __restrict__ x, __half* __restrict__ F,
                  int* __restrict__ cnt, int n) {
    int gid = blockIdx.x * 256 + threadIdx.x;
    int total = n * 32;                     // n*128/4 float4 groups
    if (gid < total) {
        float4 v = ((const float4*)x)[gid];
        uint2 p;
        p.x = h2_as_u32(__floats2half2_rn(v.x, v.y));
        p.y = h2_as_u32(__floats2half2_rn(v.z, v.w));
        ((uint2*)F)[gid] = p;
    }
    if (gid < n) cnt[gid] = 0;
}

// ---------------------------------------------------------------------------
// CSR build
// ---------------------------------------------------------------------------
__global__ void hist_kernel(const int* __restrict__ dst, int* __restrict__ cnt, int m) {
    int e = blockIdx.x * blockDim.x + threadIdx.x;
    if (e < m) atomicAdd(&cnt[dst[e]], 1);
}

__global__ void dinv_kernel(const int* __restrict__ cnt, float* __restrict__ dinv, int n) {
    int i = blockIdx.x * blockDim.x + threadIdx.x;
    if (i < n) dinv[i] = rsqrtf((float)(cnt[i] + 1));
}

__global__ __launch_bounds__(256)
void scan_p1_kernel(const int* __restrict__ cnt, int* __restrict__ bsum, int n) {
    __shared__ int red[256];
    int base = blockIdx.x * 1024;
    int t = threadIdx.x;
    int s = 0;
#pragma unroll
    for (int j = 0; j < 4; j++) {
        int i = base + t * 4 + j;
        if (i < n) s += cnt[i];
    }
    red[t] = s;
    __syncthreads();
    for (int d = 128; d > 0; d >>= 1) {
        if (t < d) red[t] += red[t + d];
        __syncthreads();
    }
    if (t == 0) bsum[blockIdx.x] = red[0];
}

__global__ __launch_bounds__(256)
void scan_p2_kernel(const int* __restrict__ bsum, int* __restrict__ boff,
                    int* __restrict__ rowptr, int n, int nb) {
    __shared__ int sm[256];
    int t = threadIdx.x;
    int v = (t < nb) ? bsum[t] : 0;
    sm[t] = v;
    __syncthreads();
    for (int d = 1; d < 256; d <<= 1) {
        int u = (t >= d) ? sm[t - d] : 0;
        __syncthreads();
        sm[t] += u;
        __syncthreads();
    }
    if (t < nb) boff[t] = sm[t] - v;
    if (t == 255) rowptr[n] = sm[255];
}

__global__ __launch_bounds__(256)
void scan_p3_kernel(const int* __restrict__ cnt, const int* __restrict__ boff,
                    int* __restrict__ rowptr, int* __restrict__ cursor, int n) {
    __shared__ int sm[256];
    int base = blockIdx.x * 1024;
    int t = threadIdx.x;
    int c[4];
    int s = 0;
#pragma unroll
    for (int j = 0; j < 4; j++) {
        int i = base + t * 4 + j;
        c[j] = (i < n) ? cnt[i] : 0;
        s += c[j];
    }
    sm[t] = s;
    __syncthreads();
    for (int d = 1; d < 256; d <<= 1) {
        int u = (t >= d) ? sm[t - d] : 0;
        __syncthreads();
        sm[t] += u;
        __syncthreads();
    }
    int run = boff[blockIdx.x] + sm[t] - s;
#pragma unroll
    for (int j = 0; j < 4; j++) {
        int i = base + t * 4 + j;
        if (i < n) { rowptr[i] = run; cursor[i] = run; }
        run += c[j];
    }
}

__global__ void fill_kernel(const int* __restrict__ src, const int* __restrict__ dst,
                            int* __restrict__ cursor, int* __restrict__ esrc, int m) {
    int e = blockIdx.x * blockDim.x + threadIdx.x;
    if (e >= m) return;
    int s = src[e];
    int d = dst[e];
    int pos = atomicAdd(&cursor[d], 1);
    esrc[pos] = s;
}

// ---------------------------------------------------------------------------
// Fused W prep: fp32 W[K,N] -> fp16 hi + fp16 residual lo, transposed [n][k].
// ---------------------------------------------------------------------------
__device__ __forceinline__ void wsplit(const float* W, unsigned short* hi,
                                       unsigned short* lo, int idx, int K, int N) {
    int n = idx % N;
    int k = idx / N;
    float w = W[idx];
    __half h = __float2half_rn(w);
    __half l = __float2half_rn(w - __half2float(h));
    hi[n * K + k] = __half_as_ushort(h);
    lo[n * K + k] = __half_as_ushort(l);
}

__global__ void bprep_all_kernel(const float* __restrict__ W1,
                                 const float* __restrict__ W2,
                                 const float* __restrict__ W3,
                                 unsigned short* __restrict__ b1h, unsigned short* __restrict__ b1l,
                                 unsigned short* __restrict__ b2h, unsigned short* __restrict__ b2l,
                                 unsigned short* __restrict__ b3h, unsigned short* __restrict__ b3l) {
    int idx = blockIdx.x * 256 + threadIdx.x;
    if (idx < 16384) {
        wsplit(W1, b1h, b1l, idx, 128, 128);
    } else if (idx < 16384 + 8192) {
        wsplit(W2, b2h, b2l, idx - 16384, 128, 64);
    } else if (idx < 16384 + 8192 + 4096) {
        wsplit(W3, b3h, b3l, idx - 16384 - 8192, 64, 64);
    }
}

// ---------------------------------------------------------------------------
// Tensor-core GEMM: G[M,N] = fp16( dinv[r] * (A[M,K] @ W[K,N]) ), A fp16.
// cp.async copy staging, K-chunked (KC=64), 2 fp16 mma passes per k-step.
// ---------------------------------------------------------------------------
template <int K, int N>
__global__ __launch_bounds__(256, 3)
void gemm_mma_kernel(const __half* __restrict__ A,
                     const unsigned short* __restrict__ Bhi,
                     const unsigned short* __restrict__ Blo,
                     const float* __restrict__ dinv,
                     __half* __restrict__ C, int M) {
    constexpr int KC = 64;
    constexpr int NK = K / KC;
    constexpr int SA = (KC + 8) * 2;     // 144B padded row stride
    constexpr int ABY = 128 * SA;        // 18432
    extern __shared__ char smem[];
    char* sA  = smem;
    char* sBh = smem + ABY;
    char* sBl = smem + ABY + N * SA;

    const int tid = threadIdx.x;
    const int wid = tid >> 5;
    const int lane = tid & 31;
    const int rowBase = blockIdx.x * 128;

    constexpr int NCH = N / 8;
    float acc[NCH][4];
#pragma unroll
    for (int i = 0; i < NCH; i++) {
        acc[i][0] = 0.f; acc[i][1] = 0.f; acc[i][2] = 0.f; acc[i][3] = 0.f;
    }

    const uint32_t aS = smem_u32(sA);
    const uint32_t bH = smem_u32(sBh);
    const uint32_t bL = smem_u32(sBl);
    const uint32_t aoff = (uint32_t)(wid * 16 + (lane & 15)) * SA + (uint32_t)(lane >> 4) * 16;
    const uint32_t boff = (uint32_t)(lane & 7) * SA + (uint32_t)((lane >> 3) & 1) * 16;

    for (int kc = 0; kc < NK; kc++) {
        if (kc) __syncthreads();   // smem reuse fence

        // B chunk: N rows x 64 k (8 x 16B per row), fire-and-forget
        for (int i = tid; i < N * 8; i += 256) {
            int r = i >> 3, c = i & 7;
            cp_async16(bH + (uint32_t)(r * SA + c * 16),
                       &Bhi[(size_t)r * K + kc * KC + c * 8]);
            cp_async16(bL + (uint32_t)(r * SA + c * 16),
                       &Blo[(size_t)r * K + kc * KC + c * 8]);
        }
        // A chunk: 128 rows x 64 k fp16 (8 x 16B per row)
        for (int i = tid; i < 128 * 8; i += 256) {
            int r = i >> 3, c = i & 7;
            int row = rowBase + r;
            if (row < M)
                cp_async16(aS + (uint32_t)(r * SA + c * 16),
                           &A[(size_t)row * K + kc * KC + c * 8]);
            // rows >= M: stale smem; those output rows are never stored
        }
        cp_async_wait_all();
        __syncthreads();

#pragma unroll
        for (int kk = 0; kk < KC / 16; kk++) {
            uint32_t a0, a1, a2, a3;
            ldsm_x4(a0, a1, a2, a3, aS + aoff + kk * 32);
#pragma unroll
            for (int nc = 0; nc < NCH; nc++) {
                uint32_t bo = (uint32_t)(nc * 8) * SA + boff + kk * 32;
                uint32_t h0, h1, l0, l1;
                ldsm_x2(h0, h1, bH + bo);
                ldsm_x2(l0, l1, bL + bo);
                mma_fp16(acc[nc], a0, a1, a2, a3, h0, h1);
                mma_fp16(acc[nc], a0, a1, a2, a3, l0, l1);
            }
        }
    }

    // epilogue: scale by dinv[row], convert to fp16, store
    int r0 = rowBase + wid * 16 + (lane >> 2);
    int c0 = (lane & 3) * 2;
    float s0 = (r0 < M)     ? dinv[r0]     : 0.f;
    float s1 = (r0 + 8 < M) ? dinv[r0 + 8] : 0.f;
#pragma unroll
    for (int nc = 0; nc < NCH; nc++) {
        if (r0 < M)
            *(__half2*)&C[(size_t)r0 * N + nc * 8 + c0] =
                __floats2half2_rn(acc[nc][0] * s0, acc[nc][1] * s0);
        if (r0 + 8 < M)
            *(__half2*)&C[(size_t)(r0 + 8) * N + nc * 8 + c0] =
                __floats2half2_rn(acc[nc][2] * s1, acc[nc][3] * s1);
    }
}

// ---------------------------------------------------------------------------
// CSR pull aggregation on fp16 G: out_i = b + dinv_i*(G_i + sum G_src).
// OUTHALF=1 -> fp16 feature output; else fp32 (final layer -> d_out).
// ---------------------------------------------------------------------------
template <int F, int RELU, int OUTHALF>
__global__ __launch_bounds__(256)
void aggregate_kernel(const __half* __restrict__ G,
                      const int* __restrict__ rowptr,
                      const int* __restrict__ esrc,
                      const float* __restrict__ dinv,
                      const float* __restrict__ bias,
                      void* __restrict__ Outp, int n) {
    constexpr int L = F / 4;          // lanes per node
    constexpr int NB = 256 / L;       // nodes per block
    int i = blockIdx.x * NB + (threadIdx.x / L);
    int c = threadIdx.x % L;          // 8B chunk index
    if (i >= n) return;

    const uint2* Gc = (const uint2*)G + c;
    constexpr int RS = F / 4;

    float2 a0, a1;
    {
        uint2 u = __ldg(&Gc[(size_t)i * RS]);
        a0 = __half22float2(*reinterpret_cast<__half2*>(&u.x));
        a1 = __half22float2(*reinterpret_cast<__half2*>(&u.y));
    }

    int k   = rowptr[i];
    int end = rowptr[i + 1];

    for (; k + 3 < end; k += 4) {
        int s0 = __ldg(&esrc[k]);
        int s1 = __ldg(&esrc[k + 1]);
        int s2 = __ldg(&esrc[k + 2]);
        int s3 = __ldg(&esrc[k + 3]);
        uint2 u0 = __ldg(&Gc[(size_t)s0 * RS]);
        uint2 u1 = __ldg(&Gc[(size_t)s1 * RS]);
        uint2 u2 = __ldg(&Gc[(size_t)s2 * RS]);
        uint2 u3 = __ldg(&Gc[(size_t)s3 * RS]);
        float2 f;
        f = __half22float2(*reinterpret_cast<__half2*>(&u0.x)); a0.x += f.x; a0.y += f.y;
        f = __half22float2(*reinterpret_cast<__half2*>(&u0.y)); a1.x += f.x; a1.y += f.y;
        f = __half22float2(*reinterpret_cast<__half2*>(&u1.x)); a0.x += f.x; a0.y += f.y;
        f = __half22float2(*reinterpret_cast<__half2*>(&u1.y)); a1.x += f.x; a1.y += f.y;
        f = __half22float2(*reinterpret_cast<__half2*>(&u2.x)); a0.x += f.x; a0.y += f.y;
        f = __half22float2(*reinterpret_cast<__half2*>(&u2.y)); a1.x += f.x; a1.y += f.y;
        f = __half22float2(*reinterpret_cast<__half2*>(&u3.x)); a0.x += f.x; a0.y += f.y;
        f = __half22float2(*reinterpret_cast<__half2*>(&u3.y)); a1.x += f.x; a1.y += f.y;
    }
    for (; k < end; k++) {
        int s0 = __ldg(&esrc[k]);
        uint2 u0 = __ldg(&Gc[(size_t)s0 * RS]);
        float2 f;
        f = __half22float2(*reinterpret_cast<__half2*>(&u0.x)); a0.x += f.x; a0.y += f.y;
        f = __half22float2(*reinterpret_cast<__half2*>(&u0.y)); a1.x += f.x; a1.y += f.y;
    }

    float di = dinv[i];
    float4 b = ((const float4*)bias)[c];
    float4 o;
    o.x = fmaf(a0.x, di, b.x);
    o.y = fmaf(a0.y, di, b.y);
    o.z = fmaf(a1.x, di, b.z);
    o.w = fmaf(a1.y, di, b.w);
    if (RELU) {
        o.x = fmaxf(o.x, 0.f); o.y = fmaxf(o.y, 0.f);
        o.z = fmaxf(o.z, 0.f); o.w = fmaxf(o.w, 0.f);
    }
    if (OUTHALF) {
        __half* Out = (__half*)Outp;
        uint2 p;
        p.x = h2_as_u32(__floats2half2_rn(o.x, o.y));
        p.y = h2_as_u32(__floats2half2_rn(o.z, o.w));
        *(uint2*)&Out[(size_t)i * F + c * 4] = p;
    } else {
        ((float4*)Outp)[(size_t)i * L + c] = o;
    }
}

// ---------------------------------------------------------------------------
// Launch (gemm1 = launch #5 for the ncu -s 5 -c 1 window)
// ---------------------------------------------------------------------------
extern "C" void kernel_launch(void* const* d_in, const int* in_sizes, int n_in,
                              void* d_out, int out_size) {
    const float* x  = (const float*)d_in[0];
    const int*   ei = (const int*)  d_in[1];
    const float* W1 = (const float*)d_in[2];
    const float* b1 = (const float*)d_in[3];
    const float* W2 = (const float*)d_in[4];
    const float* b2 = (const float*)d_in[5];
    const float* W3 = (const float*)d_in[6];
    const float* b3 = (const float*)d_in[7];

    const int n = in_sizes[0] / 128;
    const int m = in_sizes[1] / 2;
    const int* src = ei;
    const int* dst = ei + m;

    float* dinv;
    __half *G, *F;
    int *cnt, *rowptr, *cursor, *bsum, *boff, *esrc;
    unsigned short *b1h, *b1l, *b2h, *b2l, *b3h, *b3l;
    cudaGetSymbolAddress((void**)&G,      g_G);
    cudaGetSymbolAddress((void**)&F,      g_F);
    cudaGetSymbolAddress((void**)&cnt,    g_cnt);
    cudaGetSymbolAddress((void**)&rowptr, g_rowptr);
    cudaGetSymbolAddress((void**)&cursor, g_cursor);
    cudaGetSymbolAddress((void**)&dinv,   g_dinv);
    cudaGetSymbolAddress((void**)&esrc,   g_esrc);
    cudaGetSymbolAddress((void**)&bsum,   g_bsum);
    cudaGetSymbolAddress((void**)&boff,   g_boff);
    cudaGetSymbolAddress((void**)&b1h,    g_B1h);
    cudaGetSymbolAddress((void**)&b1l,    g_B1l);
    cudaGetSymbolAddress((void**)&b2h,    g_B2h);
    cudaGetSymbolAddress((void**)&b2l,    g_B2l);
    cudaGetSymbolAddress((void**)&b3h,    g_B3h);
    cudaGetSymbolAddress((void**)&b3l,    g_B3l);

    const int T = 256;
    const int nb = (n + 1023) / 1024;

    constexpr int SM1 = 18432 + 2 * (128 * 144);  // 55296
    constexpr int SM2 = 18432 + 2 * (64 * 144);   // 36864
    constexpr int SM3 = 18432 + 2 * (64 * 144);   // 36864
    cudaFuncSetAttribute(gemm_mma_kernel<128, 128>, cudaFuncAttributeMaxDynamicSharedMemorySize, SM1);
    cudaFuncSetAttribute(gemm_mma_kernel<128, 64>,  cudaFuncAttributeMaxDynamicSharedMemorySize, SM2);
    cudaFuncSetAttribute(gemm_mma_kernel<64, 64>,   cudaFuncAttributeMaxDynamicSharedMemorySize, SM3);

    const int GB = (n + 127) / 128;

    // 1-4: x->fp16 (+cnt zero), degree, dinv, W prep
    xprep_kernel<<<(n * 32 + 255) / 256, 256>>>(x, F, cnt, n);
    hist_kernel<<<(m + T - 1) / T, T>>>(dst, cnt, m);
    dinv_kernel<<<(n + T - 1) / T, T>>>(cnt, dinv, n);
    bprep_all_kernel<<<(16384 + 8192 + 4096 + 255) / 256, 256>>>(
        W1, W2, W3, b1h, b1l, b2h, b2l, b3h, b3l);
    // 5: GEMM1 (ncu window) — reads fp16 x image in F, writes G
    gemm_mma_kernel<128, 128><<<GB, 256, SM1>>>(F, b1h, b1l, dinv, G, n);
    // 6-9: CSR scan + fill
    scan_p1_kernel<<<nb, 256>>>(cnt, bsum, n);
    scan_p2_kernel<<<1, 256>>>(bsum, boff, rowptr, n, nb);
    scan_p3_kernel<<<nb, 256>>>(cnt, boff, rowptr, cursor, n);
    fill_kernel<<<(m + T - 1) / T, T>>>(src, dst, cursor, esrc, m);
    // 10-14: aggregate / gemm chain
    aggregate_kernel<128, 1, 1><<<(n + 7) / 8, 256>>>(G, rowptr, esrc, dinv, b1, F, n);
    gemm_mma_kernel<128, 64><<<GB, 256, SM2>>>(F, b2h, b2l, dinv, G, n);
    aggregate_kernel<64, 1, 1><<<(n + 15) / 16, 256>>>(G, rowptr, esrc, dinv, b2, F, n);
    gemm_mma_kernel<64, 64><<<GB, 256, SM3>>>(F, b3h, b3l, dinv, G, n);
    aggregate_kernel<64, 0, 0><<<(n + 15) / 16, 256>>>(G, rowptr, esrc, dinv, b3,
                                                       d_out, n);
}